// round 2
// baseline (speedup 1.0000x reference)
#include <cuda_runtime.h>
#include <math.h>
#include <stdint.h>

#define DD 768
#define G3 2304            // 3*DD
#define S_MAX 2048
#define E_MAX 32768
#define N_MAX 100000
#define R_MAX 1000

// ---------------- scratch (static __device__, no allocation) ----------------
__device__ float g_gi0[G3];                          // enc @ W_ih^T + b_ih
__device__ float g_sub[(size_t)S_MAX * DD];          // tanh(mask @ W_sub^T + b_sub)
__device__ float g_r0 [(size_t)S_MAX * DD];          // GRU(enc, sub)
__device__ float g_bufG[(size_t)S_MAX * G3];         // gh0, then reused for giH
__device__ float g_ghR[(size_t)R_MAX * G3];          // rel @ W_hh^T + b_hh
__device__ float g_rjw[(size_t)E_MAX * DD];          // rj rows for winners (compact)
__device__ float g_objw[(size_t)E_MAX * DD];         // obj rows for winners (compact)
__device__ int   g_best[N_MAX];
__device__ int   g_seedpos[N_MAX];
__device__ int   g_winedge[E_MAX];
__device__ int   g_winofnode[N_MAX];
__device__ int   g_wcount;

// ---------------- helpers ----------------
__device__ __forceinline__ float fast_tanh(float x) {
    float y; asm("tanh.approx.f32 %0, %1;" : "=f"(y) : "f"(x)); return y;
}
__device__ __forceinline__ float fast_sigmoid(float x) {
    return 1.0f / (1.0f + __expf(-x));
}

// ---------------- small kernels ----------------
__global__ void k_init(int N) {
    int i = blockIdx.x * blockDim.x + threadIdx.x;
    if (i < N) { g_best[i] = -1; g_seedpos[i] = -1; }
    if (i == 0) g_wcount = 0;
}

__global__ void k_seed(const int* __restrict__ seeds, int S, int stride) {
    int s = blockIdx.x * blockDim.x + threadIdx.x;
    if (s >= S) return;
    int node = seeds[s];
    g_seedpos[node] = s;
    atomicMax(&g_best[node], s * stride);
}

__global__ void k_edget(const int* __restrict__ heads, const int* __restrict__ tails,
                        int E, int stride) {
    int e = blockIdx.x * blockDim.x + threadIdx.x;
    if (e >= E) return;
    int pos = g_seedpos[heads[e]];
    int t = pos * stride + 1 + e;
    atomicMax(&g_best[tails[e]], t);
}

// gi0[n] = dot(enc, W_ih[n,:]) + b_ih[n]   (one warp per output)
__global__ void k_gi0(const float* __restrict__ enc, const float* __restrict__ W_ih,
                      const float* __restrict__ b_ih) {
    int warp = (blockIdx.x * blockDim.x + threadIdx.x) >> 5;
    int lane = threadIdx.x & 31;
    if (warp >= G3) return;
    const float* w = W_ih + (size_t)warp * DD;
    float s = 0.f;
    #pragma unroll 4
    for (int k = lane; k < DD; k += 32) s += enc[k] * w[k];
    #pragma unroll
    for (int off = 16; off; off >>= 1) s += __shfl_down_sync(0xffffffffu, s, off);
    if (lane == 0) g_gi0[warp] = s + b_ih[warp];
}

// ---------------- SGEMM: C[m,n] = epi( sum_k A[m,k]*W[n,k] + bias[n] ) ----------------
// NT gemm (both row-major, K contiguous). BM=BN=128, BK=8, 256 thr, 8x8 microtile.
// N must be a multiple of 128 (true for 768 / 2304). M guarded.
// EPI: 0 = bias, 1 = bias + tanh
template<int EPI>
__global__ void __launch_bounds__(256)
k_sgemm(const float* __restrict__ A, const float* __restrict__ W,
        const float* __restrict__ bias, float* __restrict__ C,
        int M, int N, int K, const int* __restrict__ mcount) {
    if (mcount) { int mc = *mcount; if (mc < M) M = mc; }
    int m0 = blockIdx.y * 128;
    int n0 = blockIdx.x * 128;
    if (m0 >= M) return;

    __shared__ __align__(16) float As[8][128];
    __shared__ __align__(16) float Bs[8][128];

    int tid  = threadIdx.x;
    int lrow = tid >> 1;            // 0..127
    int lcol = (tid & 1) * 4;       // 0 or 4
    int tx   = tid & 15;
    int ty   = tid >> 4;

    bool avalid = (m0 + lrow) < M;
    const float* Aptr = A + (size_t)(m0 + lrow) * K + lcol;
    const float* Wptr = W + (size_t)(n0 + lrow) * K + lcol;

    float acc[8][8];
    #pragma unroll
    for (int i = 0; i < 8; i++)
        #pragma unroll
        for (int j = 0; j < 8; j++) acc[i][j] = 0.f;

    for (int k0 = 0; k0 < K; k0 += 8) {
        float4 av = avalid ? *(const float4*)(Aptr + k0) : make_float4(0.f, 0.f, 0.f, 0.f);
        float4 wv = *(const float4*)(Wptr + k0);
        As[lcol + 0][lrow] = av.x; As[lcol + 1][lrow] = av.y;
        As[lcol + 2][lrow] = av.z; As[lcol + 3][lrow] = av.w;
        Bs[lcol + 0][lrow] = wv.x; Bs[lcol + 1][lrow] = wv.y;
        Bs[lcol + 2][lrow] = wv.z; Bs[lcol + 3][lrow] = wv.w;
        __syncthreads();
        #pragma unroll
        for (int kk = 0; kk < 8; kk++) {
            float a[8], b[8];
            *(float4*)(a)     = *(const float4*)&As[kk][ty * 8];
            *(float4*)(a + 4) = *(const float4*)&As[kk][ty * 8 + 4];
            *(float4*)(b)     = *(const float4*)&Bs[kk][tx * 8];
            *(float4*)(b + 4) = *(const float4*)&Bs[kk][tx * 8 + 4];
            #pragma unroll
            for (int i = 0; i < 8; i++)
                #pragma unroll
                for (int j = 0; j < 8; j++) acc[i][j] += a[i] * b[j];
        }
        __syncthreads();
    }

    #pragma unroll
    for (int i = 0; i < 8; i++) {
        int m = m0 + ty * 8 + i;
        if (m >= M) break;
        float* crow = C + (size_t)m * N + n0 + tx * 8;
        #pragma unroll
        for (int j = 0; j < 8; j++) {
            float v = acc[i][j] + bias[n0 + tx * 8 + j];
            if (EPI == 1) v = fast_tanh(v);
            crow[j] = v;
        }
    }
}

// r0 = GRU combine: gi0 (broadcast), gh0 rows (g_bufG), h = sub
__global__ void k_r0(int S) {
    int s = blockIdx.x;
    if (s >= S) return;
    const float* gh = g_bufG + (size_t)s * G3;
    const float* hb = g_sub  + (size_t)s * DD;
    float*       ro = g_r0   + (size_t)s * DD;
    for (int d = threadIdx.x; d < DD; d += blockDim.x) {
        float r = fast_sigmoid(g_gi0[d]        + gh[d]);
        float z = fast_sigmoid(g_gi0[DD + d]   + gh[DD + d]);
        float n = fast_tanh   (g_gi0[2*DD + d] + r * gh[2*DD + d]);
        ro[d] = (1.f - z) * n + z * hb[d];
    }
}

// winner compaction: edge e wins if best[tail] == its timestamp
__global__ void k_compact(const int* __restrict__ heads, const int* __restrict__ tails,
                          int E, int stride) {
    int e = blockIdx.x * blockDim.x + threadIdx.x;
    if (e >= E) return;
    int pos = g_seedpos[heads[e]];
    int t = pos * stride + 1 + e;
    int tl = tails[e];
    if (g_best[tl] == t) {
        int w = atomicAdd(&g_wcount, 1);
        g_winedge[w] = e;
        g_winofnode[tl] = w;
    }
}

// rj rows for winners: GRU combine of giH[head] (g_bufG), ghR[type], h = rel[type]
__global__ void k_rj(const int* __restrict__ heads, const int* __restrict__ types,
                     const float* __restrict__ rel) {
    int w = blockIdx.x;
    if (w >= g_wcount) return;
    int e = g_winedge[w];
    int head = heads[e];
    int typ  = types[e];
    const float* gi = g_bufG + (size_t)head * G3;
    const float* gh = g_ghR  + (size_t)typ  * G3;
    const float* hv = rel    + (size_t)typ  * DD;
    float*       rj = g_rjw  + (size_t)w    * DD;
    for (int d = threadIdx.x; d < DD; d += blockDim.x) {
        float r = fast_sigmoid(gi[d]        + gh[d]);
        float z = fast_sigmoid(gi[DD + d]   + gh[DD + d]);
        float n = fast_tanh   (gi[2*DD + d] + r * gh[2*DD + d]);
        rj[d] = (1.f - z) * n + z * hv[d];
    }
}

// final gather: out[i] = default / sub[seed] / objw[winner] per best[] state
__global__ void k_final(const int* __restrict__ n2n, const int* __restrict__ oldnd,
                        const float* __restrict__ defnd, float* __restrict__ out,
                        int N, int stride) {
    int node = blockIdx.x;
    if (node >= N) return;
    int id = n2n[oldnd[node]];
    int b  = g_best[id];
    const float4* src;
    if (b < 0) {
        src = (const float4*)(defnd + (size_t)node * DD);
    } else if (b % stride == 0) {
        src = (const float4*)(g_sub + (size_t)(b / stride) * DD);
    } else {
        src = (const float4*)(g_objw + (size_t)g_winofnode[id] * DD);
    }
    float4* dst = (float4*)(out + (size_t)node * DD);
    int q = threadIdx.x;           // 192 threads, one float4 each
    dst[q] = src[q];
}

// ---------------- launch ----------------
extern "C" void kernel_launch(void* const* d_in, const int* in_sizes, int n_in,
                              void* d_out, int out_size) {
    const float* enc    = (const float*)d_in[0];
    const float* smask  = (const float*)d_in[1];
    const int*   seeds  = (const int*)  d_in[2];
    const int*   eheads = (const int*)  d_in[3];
    const int*   etails = (const int*)  d_in[4];
    const int*   etype  = (const int*)  d_in[5];
    const int*   n2n    = (const int*)  d_in[6];
    const int*   oldnd  = (const int*)  d_in[7];
    const float* relemb = (const float*)d_in[8];
    const float* W_sub  = (const float*)d_in[9];
    const float* b_sub  = (const float*)d_in[10];
    const float* W_obj  = (const float*)d_in[11];
    const float* b_obj  = (const float*)d_in[12];
    const float* W_ih   = (const float*)d_in[13];
    const float* W_hh   = (const float*)d_in[14];
    const float* b_ih   = (const float*)d_in[15];
    const float* b_hh   = (const float*)d_in[16];
    const float* defnd  = (const float*)d_in[17];
    float* out = (float*)d_out;

    int S = in_sizes[2];
    int E = in_sizes[3];
    int N = in_sizes[6];
    int R = in_sizes[8] / DD;
    int stride = E + 1;

    float *p_sub, *p_r0, *p_bufG, *p_ghR, *p_rjw, *p_objw;
    int* p_wcount;
    cudaGetSymbolAddress((void**)&p_sub,    g_sub);
    cudaGetSymbolAddress((void**)&p_r0,     g_r0);
    cudaGetSymbolAddress((void**)&p_bufG,   g_bufG);
    cudaGetSymbolAddress((void**)&p_ghR,    g_ghR);
    cudaGetSymbolAddress((void**)&p_rjw,    g_rjw);
    cudaGetSymbolAddress((void**)&p_objw,   g_objw);
    cudaGetSymbolAddress((void**)&p_wcount, g_wcount);

    // 1. init best/seedpos/wcount
    k_init<<<(N + 255) / 256, 256>>>(N);
    // 2. seed scatter + seed timestamps
    k_seed<<<(S + 255) / 256, 256>>>(seeds, S, stride);
    // 3. edge timestamps
    k_edget<<<(E + 255) / 256, 256>>>(eheads, etails, E, stride);
    // 4. gi0 vector
    k_gi0<<<(G3 * 32 + 255) / 256, 256>>>(enc, W_ih, b_ih);
    // 5. sub = tanh(mask @ W_sub^T + b_sub)
    {
        dim3 g(DD / 128, (S + 127) / 128);
        k_sgemm<1><<<g, 256>>>(smask, W_sub, b_sub, p_sub, S, DD, DD, nullptr);
    }
    // 6. gh0 = sub @ W_hh^T + b_hh  -> bufG
    {
        dim3 g(G3 / 128, (S + 127) / 128);
        k_sgemm<0><<<g, 256>>>(p_sub, W_hh, b_hh, p_bufG, S, G3, DD, nullptr);
    }
    // 7. r0 combine
    k_r0<<<S, 256>>>(S);
    // 8. giH = r0 @ W_ih^T + b_ih  -> bufG (reuse)
    {
        dim3 g(G3 / 128, (S + 127) / 128);
        k_sgemm<0><<<g, 256>>>(p_r0, W_ih, b_ih, p_bufG, S, G3, DD, nullptr);
    }
    // 9. ghR = rel @ W_hh^T + b_hh
    {
        dim3 g(G3 / 128, (R + 127) / 128);
        k_sgemm<0><<<g, 256>>>(relemb, W_hh, b_hh, p_ghR, R, G3, DD, nullptr);
    }
    // 10. winner compaction
    k_compact<<<(E + 255) / 256, 256>>>(eheads, etails, E, stride);
    // 11. rj rows for winners
    k_rj<<<E, 256>>>(eheads, etype, relemb);
    // 12. objw = tanh(rjw @ W_obj^T + b_obj), M clamped by wcount
    {
        dim3 g(DD / 128, (E + 127) / 128);
        k_sgemm<1><<<g, 256>>>(p_rjw, W_obj, b_obj, p_objw, E, DD, DD, p_wcount);
    }
    // 13. final gather
    k_final<<<N, 192>>>(n2n, oldnd, defnd, out, N, stride);
}

// round 4
// speedup vs baseline: 1.8919x; 1.8919x over previous
#include <cuda_runtime.h>
#include <cuda_bf16.h>
#include <math.h>
#include <stdint.h>

#define DD 768
#define G3 2304            // 3*DD
#define S_MAX 2048
#define E_MAX 32768
#define N_MAX 100000
#define R_MAX 1000

// ---------------- scratch (static __device__, no allocation) ----------------
__device__ float g_gi0[G3];
__device__ float g_sub[(size_t)S_MAX * DD];
__device__ float g_r0 [(size_t)S_MAX * DD];
__device__ float g_bufG[(size_t)S_MAX * G3];
__device__ float g_ghR[(size_t)R_MAX * G3];
__device__ float g_rjw[(size_t)E_MAX * DD];
__device__ float g_objw[(size_t)E_MAX * DD];
__device__ int   g_best[N_MAX];
__device__ int   g_seedpos[N_MAX];
__device__ int   g_winedge[E_MAX];
__device__ int   g_winofnode[N_MAX];
__device__ int   g_wcount;

// ---------------- helpers ----------------
__device__ __forceinline__ float fast_tanh(float x) {
    float y; asm("tanh.approx.f32 %0, %1;" : "=f"(y) : "f"(x)); return y;
}
__device__ __forceinline__ float fast_sigmoid(float x) {
    return 1.0f / (1.0f + __expf(-x));
}
__device__ __forceinline__ uint32_t smem_u32(const void* p) {
    uint32_t a;
    asm("{ .reg .u64 t; cvta.to.shared.u64 t, %1; cvt.u32.u64 %0, t; }" : "=r"(a) : "l"(p));
    return a;
}
#define SWZ64(o) ((o) ^ (((o) >> 3) & 0x30))

__device__ __forceinline__ void ldsm4(uint32_t addr, uint32_t* r) {
    asm volatile("ldmatrix.sync.aligned.m8n8.x4.shared.b16 {%0,%1,%2,%3}, [%4];"
                 : "=r"(r[0]), "=r"(r[1]), "=r"(r[2]), "=r"(r[3]) : "r"(addr));
}
__device__ __forceinline__ void mma_bf16(float* c, const uint32_t* a, const uint32_t* b) {
    asm volatile(
        "mma.sync.aligned.m16n8k16.row.col.f32.bf16.bf16.f32 "
        "{%0,%1,%2,%3}, {%4,%5,%6,%7}, {%8,%9}, {%0,%1,%2,%3};"
        : "+f"(c[0]), "+f"(c[1]), "+f"(c[2]), "+f"(c[3])
        : "r"(a[0]), "r"(a[1]), "r"(a[2]), "r"(a[3]), "r"(b[0]), "r"(b[1]));
}
__device__ __forceinline__ void cvt8(const float* f, uint4& h, uint4& l) {
    uint32_t uh[8], ul[8];
    #pragma unroll
    for (int q = 0; q < 8; q++) {
        __nv_bfloat16 hb = __float2bfloat16(f[q]);
        float r = f[q] - __bfloat162float(hb);
        uh[q] = (uint32_t)__bfloat16_as_ushort(hb);
        ul[q] = (uint32_t)__bfloat16_as_ushort(__float2bfloat16(r));
    }
    h = make_uint4(uh[0] | (uh[1] << 16), uh[2] | (uh[3] << 16),
                   uh[4] | (uh[5] << 16), uh[6] | (uh[7] << 16));
    l = make_uint4(ul[0] | (ul[1] << 16), ul[2] | (ul[3] << 16),
                   ul[4] | (ul[5] << 16), ul[6] | (ul[7] << 16));
}

// ---------------- small kernels ----------------
__global__ void k_init(int N) {
    int i = blockIdx.x * blockDim.x + threadIdx.x;
    if (i < N) { g_best[i] = -1; g_seedpos[i] = -1; }
    if (i == 0) g_wcount = 0;
}

__global__ void k_seed(const int* __restrict__ seeds, int S, int stride) {
    int s = blockIdx.x * blockDim.x + threadIdx.x;
    if (s >= S) return;
    int node = seeds[s];
    g_seedpos[node] = s;
    atomicMax(&g_best[node], s * stride);
}

__global__ void k_edget(const int* __restrict__ heads, const int* __restrict__ tails,
                        int E, int stride) {
    int e = blockIdx.x * blockDim.x + threadIdx.x;
    if (e >= E) return;
    int pos = g_seedpos[heads[e]];
    int t = pos * stride + 1 + e;
    atomicMax(&g_best[tails[e]], t);
}

__global__ void k_gi0(const float* __restrict__ enc, const float* __restrict__ W_ih,
                      const float* __restrict__ b_ih) {
    int warp = (blockIdx.x * blockDim.x + threadIdx.x) >> 5;
    int lane = threadIdx.x & 31;
    if (warp >= G3) return;
    const float* w = W_ih + (size_t)warp * DD;
    float s = 0.f;
    #pragma unroll 4
    for (int k = lane; k < DD; k += 32) s += enc[k] * w[k];
    #pragma unroll
    for (int off = 16; off; off >>= 1) s += __shfl_down_sync(0xffffffffu, s, off);
    if (lane == 0) g_gi0[warp] = s + b_ih[warp];
}

// ---------------- bf16-split HMMA GEMM ----------------
// C[m,n] = epi( sum_k A[m,k]*W[n,k] + bias[n] ), A:[M,K], W:[N,K] row-major.
// 128x128 CTA tile, BK=32, hi/lo bf16 split: C = Ah*Bh + Al*Bh + Ah*Bl.
// SMEM: per stage 4 tiles (Ah, Al, Bh, Bl), each 128 rows x 64B, SW64 swizzle.
#define BK     32
#define TILEB  (128 * 64)        // 8192 B
#define STAGEB (4 * TILEB)       // 32768 B
#define SMEM_DYN (2 * STAGEB)    // 65536 B

template<int EPI>
__global__ void __launch_bounds__(256, 1)
k_hgemm(const float* __restrict__ A, const float* __restrict__ W,
        const float* __restrict__ bias, float* __restrict__ C,
        int M, int N, int K, const int* __restrict__ mcount) {
    if (mcount) { int mc = *mcount; if (mc < M) M = mc; }
    int m0 = blockIdx.y * 128;
    int n0 = blockIdx.x * 128;
    if (m0 >= M) return;

    extern __shared__ __align__(1024) char sm[];
    uint32_t smb = smem_u32(sm);

    int tid = threadIdx.x, lane = tid & 31, wid = tid >> 5;
    int wm = wid >> 1, wn = wid & 1;          // warp tile: rows wm*32, cols wn*64
    int g = lane >> 3, lr = lane & 7;
    uint32_t xorm = (uint32_t)((lr & 6) << 3);

    // producer mapping: thread -> (row, 16-float half)
    int prow = tid >> 1, phalf = tid & 1;
    int arow = min(m0 + prow, M - 1);
    const float4* Ap = (const float4*)(A + (size_t)arow * K) + phalf * 4;
    const float4* Wp = (const float4*)(W + (size_t)(n0 + prow) * K) + phalf * 4;
    uint32_t so0 = SWZ64((uint32_t)(prow * 64 + phalf * 32));
    uint32_t so1 = SWZ64((uint32_t)(prow * 64 + phalf * 32 + 16));

    float acc[2][8][4];
    #pragma unroll
    for (int i = 0; i < 2; i++)
        #pragma unroll
        for (int j = 0; j < 8; j++)
            #pragma unroll
            for (int q = 0; q < 4; q++) acc[i][j][q] = 0.f;

    const int NC = K / BK;

    // ---- producer store of one chunk into stage p ----
    auto store_stage = [&](int p, float4* ra, float4* rw) {
        char* st = sm + p * STAGEB;
        uint4 h, l;
        cvt8((const float*)ra, h, l);
        *(uint4*)(st + so0) = h;               // Ah
        *(uint4*)(st + TILEB + so0) = l;       // Al
        cvt8((const float*)ra + 8, h, l);
        *(uint4*)(st + so1) = h;
        *(uint4*)(st + TILEB + so1) = l;
        cvt8((const float*)rw, h, l);
        *(uint4*)(st + 2 * TILEB + so0) = h;   // Bh
        *(uint4*)(st + 3 * TILEB + so0) = l;   // Bl
        cvt8((const float*)rw + 8, h, l);
        *(uint4*)(st + 2 * TILEB + so1) = h;
        *(uint4*)(st + 3 * TILEB + so1) = l;
    };

    {   // preload chunk 0
        float4 ra[4], rw[4];
        #pragma unroll
        for (int i = 0; i < 4; i++) { ra[i] = Ap[i]; rw[i] = Wp[i]; }
        store_stage(0, ra, rw);
    }
    __syncthreads();

    for (int c = 0; c < NC; c++) {
        int p = c & 1;
        float4 na[4], nw[4];
        if (c + 1 < NC) {
            const float4* ap = Ap + (size_t)(c + 1) * (BK / 4);
            const float4* wp = Wp + (size_t)(c + 1) * (BK / 4);
            #pragma unroll
            for (int i = 0; i < 4; i++) { na[i] = ap[i]; nw[i] = wp[i]; }
        }
        // ---- MMA on stage p ----
        uint32_t stage = smb + p * STAGEB;
        #pragma unroll
        for (int ks = 0; ks < 2; ks++) {
            int kb = ks * 32;
            uint32_t ah[2][4], al[2][4], bb[4][4];
            #pragma unroll
            for (int mt = 0; mt < 2; mt++) {
                uint32_t off = (uint32_t)(wm * 32 + mt * 16 + (g & 1) * 8 + lr) * 64
                             + (((uint32_t)(kb + (g >> 1) * 16)) ^ xorm);
                ldsm4(stage + off, ah[mt]);
                ldsm4(stage + TILEB + off, al[mt]);
            }
            #pragma unroll
            for (int q = 0; q < 4; q++) {
                uint32_t off = (uint32_t)(wn * 64 + q * 16 + (g >> 1) * 8 + lr) * 64
                             + (((uint32_t)(kb + (g & 1) * 16)) ^ xorm);
                ldsm4(stage + 2 * TILEB + off, bb[q]);
            }
            #pragma unroll
            for (int mt = 0; mt < 2; mt++)
                #pragma unroll
                for (int q = 0; q < 4; q++) {
                    mma_bf16(acc[mt][2 * q],     ah[mt], bb[q]);
                    mma_bf16(acc[mt][2 * q + 1], ah[mt], bb[q] + 2);
                }
            #pragma unroll
            for (int mt = 0; mt < 2; mt++)
                #pragma unroll
                for (int q = 0; q < 4; q++) {
                    mma_bf16(acc[mt][2 * q],     al[mt], bb[q]);
                    mma_bf16(acc[mt][2 * q + 1], al[mt], bb[q] + 2);
                }
            #pragma unroll
            for (int q = 0; q < 4; q++) {
                uint32_t off = (uint32_t)(wn * 64 + q * 16 + (g >> 1) * 8 + lr) * 64
                             + (((uint32_t)(kb + (g & 1) * 16)) ^ xorm);
                ldsm4(stage + 3 * TILEB + off, bb[q]);
            }
            #pragma unroll
            for (int mt = 0; mt < 2; mt++)
                #pragma unroll
                for (int q = 0; q < 4; q++) {
                    mma_bf16(acc[mt][2 * q],     ah[mt], bb[q]);
                    mma_bf16(acc[mt][2 * q + 1], ah[mt], bb[q] + 2);
                }
        }
        if (c + 1 < NC) store_stage(p ^ 1, na, nw);
        __syncthreads();
    }

    // ---- epilogue: bias (+tanh), direct stores from fragments ----
    int lane4 = lane >> 2, lane2 = (lane & 3) * 2;
    #pragma unroll
    for (int mt = 0; mt < 2; mt++) {
        int r0 = m0 + wm * 32 + mt * 16 + lane4;
        #pragma unroll
        for (int q = 0; q < 8; q++) {
            int col = n0 + wn * 64 + q * 8 + lane2;
            float b0 = bias[col], b1 = bias[col + 1];
            float v0 = acc[mt][q][0] + b0, v1 = acc[mt][q][1] + b1;
            float v2 = acc[mt][q][2] + b0, v3 = acc[mt][q][3] + b1;
            if (EPI == 1) {
                v0 = fast_tanh(v0); v1 = fast_tanh(v1);
                v2 = fast_tanh(v2); v3 = fast_tanh(v3);
            }
            if (r0 < M)     *(float2*)(C + (size_t)r0 * N + col)       = make_float2(v0, v1);
            if (r0 + 8 < M) *(float2*)(C + (size_t)(r0 + 8) * N + col) = make_float2(v2, v3);
        }
    }
}

// r0 = GRU combine: gi0 (broadcast), gh0 rows (g_bufG), h = sub
__global__ void k_r0(int S) {
    int s = blockIdx.x;
    if (s >= S) return;
    const float* gh = g_bufG + (size_t)s * G3;
    const float* hb = g_sub  + (size_t)s * DD;
    float*       ro = g_r0   + (size_t)s * DD;
    for (int d = threadIdx.x; d < DD; d += blockDim.x) {
        float r = fast_sigmoid(g_gi0[d]        + gh[d]);
        float z = fast_sigmoid(g_gi0[DD + d]   + gh[DD + d]);
        float n = fast_tanh   (g_gi0[2*DD + d] + r * gh[2*DD + d]);
        ro[d] = (1.f - z) * n + z * hb[d];
    }
}

__global__ void k_compact(const int* __restrict__ heads, const int* __restrict__ tails,
                          int E, int stride) {
    int e = blockIdx.x * blockDim.x + threadIdx.x;
    if (e >= E) return;
    int pos = g_seedpos[heads[e]];
    int t = pos * stride + 1 + e;
    int tl = tails[e];
    if (g_best[tl] == t) {
        int w = atomicAdd(&g_wcount, 1);
        g_winedge[w] = e;
        g_winofnode[tl] = w;
    }
}

__global__ void k_rj(const int* __restrict__ heads, const int* __restrict__ types,
                     const float* __restrict__ rel) {
    int w = blockIdx.x;
    if (w >= g_wcount) return;
    int e = g_winedge[w];
    int head = heads[e];
    int typ  = types[e];
    const float* gi = g_bufG + (size_t)head * G3;
    const float* gh = g_ghR  + (size_t)typ  * G3;
    const float* hv = rel    + (size_t)typ  * DD;
    float*       rj = g_rjw  + (size_t)w    * DD;
    for (int d = threadIdx.x; d < DD; d += blockDim.x) {
        float r = fast_sigmoid(gi[d]        + gh[d]);
        float z = fast_sigmoid(gi[DD + d]   + gh[DD + d]);
        float n = fast_tanh   (gi[2*DD + d] + r * gh[2*DD + d]);
        rj[d] = (1.f - z) * n + z * hv[d];
    }
}

__global__ void k_final(const int* __restrict__ n2n, const int* __restrict__ oldnd,
                        const float* __restrict__ defnd, float* __restrict__ out,
                        int N, int stride) {
    int node = blockIdx.x;
    if (node >= N) return;
    int id = n2n[oldnd[node]];
    int b  = g_best[id];
    const float4* src;
    if (b < 0) {
        src = (const float4*)(defnd + (size_t)node * DD);
    } else if (b % stride == 0) {
        src = (const float4*)(g_sub + (size_t)(b / stride) * DD);
    } else {
        src = (const float4*)(g_objw + (size_t)g_winofnode[id] * DD);
    }
    float4* dst = (float4*)(out + (size_t)node * DD);
    dst[threadIdx.x] = src[threadIdx.x];
}

// ---------------- launch ----------------
extern "C" void kernel_launch(void* const* d_in, const int* in_sizes, int n_in,
                              void* d_out, int out_size) {
    const float* enc    = (const float*)d_in[0];
    const float* smask  = (const float*)d_in[1];
    const int*   seeds  = (const int*)  d_in[2];
    const int*   eheads = (const int*)  d_in[3];
    const int*   etails = (const int*)  d_in[4];
    const int*   etype  = (const int*)  d_in[5];
    const int*   n2n    = (const int*)  d_in[6];
    const int*   oldnd  = (const int*)  d_in[7];
    const float* relemb = (const float*)d_in[8];
    const float* W_sub  = (const float*)d_in[9];
    const float* b_sub  = (const float*)d_in[10];
    const float* W_obj  = (const float*)d_in[11];
    const float* b_obj  = (const float*)d_in[12];
    const float* W_ih   = (const float*)d_in[13];
    const float* W_hh   = (const float*)d_in[14];
    const float* b_ih   = (const float*)d_in[15];
    const float* b_hh   = (const float*)d_in[16];
    const float* defnd  = (const float*)d_in[17];
    float* out = (float*)d_out;

    int S = in_sizes[2];
    int E = in_sizes[3];
    int N = in_sizes[6];
    int R = in_sizes[8] / DD;
    int stride = E + 1;

    float *p_sub, *p_r0, *p_bufG, *p_ghR, *p_rjw, *p_objw;
    int* p_wcount;
    cudaGetSymbolAddress((void**)&p_sub,    g_sub);
    cudaGetSymbolAddress((void**)&p_r0,     g_r0);
    cudaGetSymbolAddress((void**)&p_bufG,   g_bufG);
    cudaGetSymbolAddress((void**)&p_ghR,    g_ghR);
    cudaGetSymbolAddress((void**)&p_rjw,    g_rjw);
    cudaGetSymbolAddress((void**)&p_objw,   g_objw);
    cudaGetSymbolAddress((void**)&p_wcount, g_wcount);

    cudaFuncSetAttribute(k_hgemm<0>, cudaFuncAttributeMaxDynamicSharedMemorySize, SMEM_DYN);
    cudaFuncSetAttribute(k_hgemm<1>, cudaFuncAttributeMaxDynamicSharedMemorySize, SMEM_DYN);

    // 1-3: timestamps
    k_init<<<(N + 255) / 256, 256>>>(N);
    k_seed<<<(S + 255) / 256, 256>>>(seeds, S, stride);
    k_edget<<<(E + 255) / 256, 256>>>(eheads, etails, E, stride);
    // 4: gi0 vector
    k_gi0<<<(G3 * 32 + 255) / 256, 256>>>(enc, W_ih, b_ih);
    // 5: sub = tanh(mask @ W_sub^T + b_sub)
    {
        dim3 g(DD / 128, (S + 127) / 128);
        k_hgemm<1><<<g, 256, SMEM_DYN>>>(smask, W_sub, b_sub, p_sub, S, DD, DD, nullptr);
    }
    // 6: gh0 = sub @ W_hh^T + b_hh
    {
        dim3 g(G3 / 128, (S + 127) / 128);
        k_hgemm<0><<<g, 256, SMEM_DYN>>>(p_sub, W_hh, b_hh, p_bufG, S, G3, DD, nullptr);
    }
    // 7: r0 combine
    k_r0<<<S, 256>>>(S);
    // 8: giH = r0 @ W_ih^T + b_ih
    {
        dim3 g(G3 / 128, (S + 127) / 128);
        k_hgemm<0><<<g, 256, SMEM_DYN>>>(p_r0, W_ih, b_ih, p_bufG, S, G3, DD, nullptr);
    }
    // 9: ghR = rel @ W_hh^T + b_hh
    {
        dim3 g(G3 / 128, (R + 127) / 128);
        k_hgemm<0><<<g, 256, SMEM_DYN>>>(relemb, W_hh, b_hh, p_ghR, R, G3, DD, nullptr);
    }
    // 10: winner compaction
    k_compact<<<(E + 255) / 256, 256>>>(eheads, etails, E, stride);
    // 11: rj rows for winners
    k_rj<<<E, 256>>>(eheads, etype, relemb);
    // 12: objw = tanh(rjw @ W_obj^T + b_obj), M clamped by wcount
    {
        dim3 g(DD / 128, (E + 127) / 128);
        k_hgemm<1><<<g, 256, SMEM_DYN>>>(p_rjw, W_obj, b_obj, p_objw, E, DD, DD, p_wcount);
    }
    // 13: final gather
    k_final<<<N, 192>>>(n2n, oldnd, defnd, out, N, stride);
}

// round 5
// speedup vs baseline: 2.4933x; 1.3179x over previous
#include <cuda_runtime.h>
#include <cuda_fp16.h>
#include <math.h>
#include <stdint.h>

#define DD 768
#define G3 2304            // 3*DD
#define S_MAX 2048
#define E_MAX 32768
#define N_MAX 100000
#define R_MAX 1000

// ---------------- scratch (static __device__, no allocation) ----------------
__device__ float g_gi0[G3];
__device__ float g_sub[(size_t)S_MAX * DD];        // fp32 sub (k_r0 h-term, k_final)
__device__ float g_bufG[(size_t)S_MAX * G3];       // gh0 then giH
__device__ float g_ghR[(size_t)R_MAX * G3];
__device__ float g_objw[(size_t)E_MAX * DD];
__device__ int   g_best[N_MAX];
__device__ int   g_seedpos[N_MAX];
__device__ int   g_winedge[E_MAX];
__device__ int   g_winofnode[N_MAX];
__device__ int   g_wcount;

// fp16 operand arrays
__device__ __half h_smask_h[(size_t)S_MAX * DD];
__device__ __half h_smask_l[(size_t)S_MAX * DD];
__device__ __half h_sub_h [(size_t)S_MAX * DD];
__device__ __half h_sub_l [(size_t)S_MAX * DD];
__device__ __half h_r0_h  [(size_t)S_MAX * DD];
__device__ __half h_r0_l  [(size_t)S_MAX * DD];
__device__ __half h_rel_h [(size_t)R_MAX * DD];
__device__ __half h_rel_l [(size_t)R_MAX * DD];
__device__ __half h_rjw_h [(size_t)E_MAX * DD];
__device__ __half h_rjw_l [(size_t)E_MAX * DD];
__device__ __half h_Wsub[(size_t)DD * DD];
__device__ __half h_Whh [(size_t)G3 * DD];
__device__ __half h_Wih [(size_t)G3 * DD];
__device__ __half h_Wobj[(size_t)DD * DD];

// ---------------- helpers ----------------
__device__ __forceinline__ float fast_tanh(float x) {
    float y; asm("tanh.approx.f32 %0, %1;" : "=f"(y) : "f"(x)); return y;
}
__device__ __forceinline__ float fast_sigmoid(float x) {
    return 1.0f / (1.0f + __expf(-x));
}
__device__ __forceinline__ uint32_t smem_u32(const void* p) {
    uint32_t a;
    asm("{ .reg .u64 t; cvta.to.shared.u64 t, %1; cvt.u32.u64 %0, t; }" : "=r"(a) : "l"(p));
    return a;
}
#define SWZ64(o) ((o) ^ (((o) >> 3) & 0x30))

__device__ __forceinline__ void ldsm4(uint32_t addr, uint32_t* r) {
    asm volatile("ldmatrix.sync.aligned.m8n8.x4.shared.b16 {%0,%1,%2,%3}, [%4];"
                 : "=r"(r[0]), "=r"(r[1]), "=r"(r[2]), "=r"(r[3]) : "r"(addr));
}
__device__ __forceinline__ void mma_fp16(float* c, const uint32_t* a, const uint32_t* b) {
    asm volatile(
        "mma.sync.aligned.m16n8k16.row.col.f32.f16.f16.f32 "
        "{%0,%1,%2,%3}, {%4,%5,%6,%7}, {%8,%9}, {%0,%1,%2,%3};"
        : "+f"(c[0]), "+f"(c[1]), "+f"(c[2]), "+f"(c[3])
        : "r"(a[0]), "r"(a[1]), "r"(a[2]), "r"(a[3]), "r"(b[0]), "r"(b[1]));
}
__device__ __forceinline__ void cp16(uint32_t saddr, const void* g) {
    asm volatile("cp.async.cg.shared.global [%0], [%1], 16;" :: "r"(saddr), "l"(g));
}
__device__ __forceinline__ void cp_commit() {
    asm volatile("cp.async.commit_group;" ::: "memory");
}
template<int NN>
__device__ __forceinline__ void cp_wait() {
    asm volatile("cp.async.wait_group %0;" :: "n"(NN) : "memory");
}

// ---------------- small kernels ----------------
__global__ void k_init(int N) {
    int i = blockIdx.x * blockDim.x + threadIdx.x;
    if (i < N) { g_best[i] = -1; g_seedpos[i] = -1; }
    if (i == 0) g_wcount = 0;
}

__global__ void k_seed(const int* __restrict__ seeds, int S, int stride) {
    int s = blockIdx.x * blockDim.x + threadIdx.x;
    if (s >= S) return;
    int node = seeds[s];
    g_seedpos[node] = s;
    atomicMax(&g_best[node], s * stride);
}

__global__ void k_edget(const int* __restrict__ heads, const int* __restrict__ tails,
                        int E, int stride) {
    int e = blockIdx.x * blockDim.x + threadIdx.x;
    if (e >= E) return;
    int pos = g_seedpos[heads[e]];
    int t = pos * stride + 1 + e;
    atomicMax(&g_best[tails[e]], t);
}

__global__ void k_gi0(const float* __restrict__ enc, const float* __restrict__ W_ih,
                      const float* __restrict__ b_ih) {
    int warp = (blockIdx.x * blockDim.x + threadIdx.x) >> 5;
    int lane = threadIdx.x & 31;
    if (warp >= G3) return;
    const float* w = W_ih + (size_t)warp * DD;
    float s = 0.f;
    #pragma unroll 4
    for (int k = lane; k < DD; k += 32) s += enc[k] * w[k];
    #pragma unroll
    for (int off = 16; off; off >>= 1) s += __shfl_down_sync(0xffffffffu, s, off);
    if (lane == 0) g_gi0[warp] = s + b_ih[warp];
}

// conversion prepasses
__global__ void k_cvt_single(const float* __restrict__ x, __half* __restrict__ h, int n) {
    int i = blockIdx.x * blockDim.x + threadIdx.x;
    if (i < n) h[i] = __float2half(x[i]);
}
__global__ void k_cvt_split(const float* __restrict__ x, __half* __restrict__ h,
                            __half* __restrict__ l, int n) {
    int i = blockIdx.x * blockDim.x + threadIdx.x;
    if (i >= n) return;
    float v = x[i];
    __half hv = __float2half(v);
    h[i] = hv;
    l[i] = __float2half(v - __half2float(hv));
}

// ---------------- fp16 2-pass HMMA GEMM ----------------
// C[m,n] = epi( sum_k A[m,k]*W[n,k] + bias[n] ), A = Ah+Al (fp16 split), W fp16.
// 128x128 CTA tile, BK=32, cp.async double buffer.
// SMEM per stage: Ah, Al, B tiles; each 128 rows x 64B, SW64 swizzle.
#define BK     32
#define TILEB  (128 * 64)        // 8192 B
#define STAGEB (3 * TILEB)       // 24576 B
#define SMEM_DYN (2 * STAGEB)    // 49152 B

template<int EPI, int DUAL>
__global__ void __launch_bounds__(256, 1)
k_hgemm(const __half* __restrict__ Ah, const __half* __restrict__ Al,
        const __half* __restrict__ Bw, const float* __restrict__ bias,
        float* __restrict__ C, __half* __restrict__ Ch, __half* __restrict__ Cl,
        int M, int N, int K, const int* __restrict__ mcount) {
    if (mcount) { int mc = *mcount; if (mc < M) M = mc; }
    int m0 = blockIdx.y * 128;
    int n0 = blockIdx.x * 128;
    if (m0 >= M) return;

    extern __shared__ __align__(1024) char sm[];
    uint32_t smb = smem_u32(sm);

    int tid = threadIdx.x, lane = tid & 31, wid = tid >> 5;
    int wm = wid >> 1, wn = wid & 1;
    int g = lane >> 3, lr = lane & 7;
    uint32_t xorm = (uint32_t)((lr & 6) << 3);

    // producer mapping: 2 16B chunks per thread per tile
    int q0 = tid * 2, q1 = tid * 2 + 1;
    int row0 = q0 >> 2, seg0 = q0 & 3;
    int row1 = q1 >> 2, seg1 = q1 & 3;
    uint32_t so0 = SWZ64((uint32_t)(row0 * 64 + seg0 * 16));
    uint32_t so1 = SWZ64((uint32_t)(row1 * 64 + seg1 * 16));
    size_t aoff0 = (size_t)min(m0 + row0, M - 1) * K + seg0 * 8;
    size_t aoff1 = (size_t)min(m0 + row1, M - 1) * K + seg1 * 8;
    size_t boff0 = (size_t)(n0 + row0) * K + seg0 * 8;
    size_t boff1 = (size_t)(n0 + row1) * K + seg1 * 8;

    const int NC = K / BK;

    auto issue = [&](int c, int p) {
        uint32_t st = smb + p * STAGEB;
        int kc = c * BK;
        cp16(st + so0,             Ah + aoff0 + kc);
        cp16(st + so1,             Ah + aoff1 + kc);
        cp16(st + TILEB + so0,     Al + aoff0 + kc);
        cp16(st + TILEB + so1,     Al + aoff1 + kc);
        cp16(st + 2 * TILEB + so0, Bw + boff0 + kc);
        cp16(st + 2 * TILEB + so1, Bw + boff1 + kc);
        cp_commit();
    };

    float acc[2][8][4];
    #pragma unroll
    for (int i = 0; i < 2; i++)
        #pragma unroll
        for (int j = 0; j < 8; j++)
            #pragma unroll
            for (int q = 0; q < 4; q++) acc[i][j][q] = 0.f;

    issue(0, 0);

    for (int c = 0; c < NC; c++) {
        int p = c & 1;
        if (c + 1 < NC) { issue(c + 1, p ^ 1); cp_wait<1>(); }
        else            { cp_wait<0>(); }
        __syncthreads();

        uint32_t stage = smb + p * STAGEB;
        #pragma unroll
        for (int ks = 0; ks < 2; ks++) {
            uint32_t kb = (uint32_t)(ks * 32);
            uint32_t ah[2][4], al[2][4], bb[4][4];
            #pragma unroll
            for (int mt = 0; mt < 2; mt++) {
                uint32_t off = (uint32_t)(wm * 32 + mt * 16 + (g & 1) * 8 + lr) * 64
                             + ((kb + (g >> 1) * 16) ^ xorm);
                ldsm4(stage + off, ah[mt]);
                ldsm4(stage + TILEB + off, al[mt]);
            }
            #pragma unroll
            for (int q = 0; q < 4; q++) {
                uint32_t off = (uint32_t)(wn * 64 + q * 16 + (g >> 1) * 8 + lr) * 64
                             + ((kb + (g & 1) * 16) ^ xorm);
                ldsm4(stage + 2 * TILEB + off, bb[q]);
            }
            #pragma unroll
            for (int mt = 0; mt < 2; mt++)
                #pragma unroll
                for (int q = 0; q < 4; q++) {
                    mma_fp16(acc[mt][2 * q],     ah[mt], bb[q]);
                    mma_fp16(acc[mt][2 * q + 1], ah[mt], bb[q] + 2);
                }
            #pragma unroll
            for (int mt = 0; mt < 2; mt++)
                #pragma unroll
                for (int q = 0; q < 4; q++) {
                    mma_fp16(acc[mt][2 * q],     al[mt], bb[q]);
                    mma_fp16(acc[mt][2 * q + 1], al[mt], bb[q] + 2);
                }
        }
        __syncthreads();
    }

    // ---- epilogue ----
    int lane4 = lane >> 2, lane2 = (lane & 3) * 2;
    #pragma unroll
    for (int mt = 0; mt < 2; mt++) {
        int r0 = m0 + wm * 32 + mt * 16 + lane4;
        #pragma unroll
        for (int q = 0; q < 8; q++) {
            int col = n0 + wn * 64 + q * 8 + lane2;
            float b0 = bias[col], b1 = bias[col + 1];
            float v0 = acc[mt][q][0] + b0, v1 = acc[mt][q][1] + b1;
            float v2 = acc[mt][q][2] + b0, v3 = acc[mt][q][3] + b1;
            if (EPI == 1) {
                v0 = fast_tanh(v0); v1 = fast_tanh(v1);
                v2 = fast_tanh(v2); v3 = fast_tanh(v3);
            }
            if (r0 < M) {
                *(float2*)(C + (size_t)r0 * N + col) = make_float2(v0, v1);
                if (DUAL) {
                    __half h0 = __float2half(v0), h1 = __float2half(v1);
                    *(__half2*)(Ch + (size_t)r0 * N + col) = __halves2half2(h0, h1);
                    *(__half2*)(Cl + (size_t)r0 * N + col) = __halves2half2(
                        __float2half(v0 - __half2float(h0)),
                        __float2half(v1 - __half2float(h1)));
                }
            }
            if (r0 + 8 < M) {
                *(float2*)(C + (size_t)(r0 + 8) * N + col) = make_float2(v2, v3);
                if (DUAL) {
                    __half h2 = __float2half(v2), h3 = __float2half(v3);
                    *(__half2*)(Ch + (size_t)(r0 + 8) * N + col) = __halves2half2(h2, h3);
                    *(__half2*)(Cl + (size_t)(r0 + 8) * N + col) = __halves2half2(
                        __float2half(v2 - __half2float(h2)),
                        __float2half(v3 - __half2float(h3)));
                }
            }
        }
    }
}

// r0 = GRU combine -> fp16 hi/lo (only consumed by GEMM step 8)
__global__ void k_r0(int S) {
    int s = blockIdx.x;
    if (s >= S) return;
    const float* gh = g_bufG + (size_t)s * G3;
    const float* hb = g_sub  + (size_t)s * DD;
    __half* rh = h_r0_h + (size_t)s * DD;
    __half* rl = h_r0_l + (size_t)s * DD;
    for (int d = threadIdx.x; d < DD; d += blockDim.x) {
        float r = fast_sigmoid(g_gi0[d]        + gh[d]);
        float z = fast_sigmoid(g_gi0[DD + d]   + gh[DD + d]);
        float n = fast_tanh   (g_gi0[2*DD + d] + r * gh[2*DD + d]);
        float v = (1.f - z) * n + z * hb[d];
        __half h = __float2half(v);
        rh[d] = h;
        rl[d] = __float2half(v - __half2float(h));
    }
}

__global__ void k_compact(const int* __restrict__ heads, const int* __restrict__ tails,
                          int E, int stride) {
    int e = blockIdx.x * blockDim.x + threadIdx.x;
    if (e >= E) return;
    int pos = g_seedpos[heads[e]];
    int t = pos * stride + 1 + e;
    int tl = tails[e];
    if (g_best[tl] == t) {
        int w = atomicAdd(&g_wcount, 1);
        g_winedge[w] = e;
        g_winofnode[tl] = w;
    }
}

// rj rows for winners -> fp16 hi/lo (only consumed by GEMM step 12)
__global__ void k_rj(const int* __restrict__ heads, const int* __restrict__ types,
                     const float* __restrict__ rel) {
    int w = blockIdx.x;
    if (w >= g_wcount) return;
    int e = g_winedge[w];
    int head = heads[e];
    int typ  = types[e];
    const float* gi = g_bufG + (size_t)head * G3;
    const float* gh = g_ghR  + (size_t)typ  * G3;
    const float* hv = rel    + (size_t)typ  * DD;
    __half* rh = h_rjw_h + (size_t)w * DD;
    __half* rl = h_rjw_l + (size_t)w * DD;
    for (int d = threadIdx.x; d < DD; d += blockDim.x) {
        float r = fast_sigmoid(gi[d]        + gh[d]);
        float z = fast_sigmoid(gi[DD + d]   + gh[DD + d]);
        float n = fast_tanh   (gi[2*DD + d] + r * gh[2*DD + d]);
        float v = (1.f - z) * n + z * hv[d];
        __half h = __float2half(v);
        rh[d] = h;
        rl[d] = __float2half(v - __half2float(h));
    }
}

__global__ void k_final(const int* __restrict__ n2n, const int* __restrict__ oldnd,
                        const float* __restrict__ defnd, float* __restrict__ out,
                        int N, int stride) {
    int node = blockIdx.x;
    if (node >= N) return;
    int id = n2n[oldnd[node]];
    int b  = g_best[id];
    const float4* src;
    if (b < 0) {
        src = (const float4*)(defnd + (size_t)node * DD);
    } else if (b % stride == 0) {
        src = (const float4*)(g_sub + (size_t)(b / stride) * DD);
    } else {
        src = (const float4*)(g_objw + (size_t)g_winofnode[id] * DD);
    }
    float4* dst = (float4*)(out + (size_t)node * DD);
    dst[threadIdx.x] = src[threadIdx.x];
}

// ---------------- launch ----------------
extern "C" void kernel_launch(void* const* d_in, const int* in_sizes, int n_in,
                              void* d_out, int out_size) {
    const float* enc    = (const float*)d_in[0];
    const float* smask  = (const float*)d_in[1];
    const int*   seeds  = (const int*)  d_in[2];
    const int*   eheads = (const int*)  d_in[3];
    const int*   etails = (const int*)  d_in[4];
    const int*   etype  = (const int*)  d_in[5];
    const int*   n2n    = (const int*)  d_in[6];
    const int*   oldnd  = (const int*)  d_in[7];
    const float* relemb = (const float*)d_in[8];
    const float* W_sub  = (const float*)d_in[9];
    const float* b_sub  = (const float*)d_in[10];
    const float* W_obj  = (const float*)d_in[11];
    const float* b_obj  = (const float*)d_in[12];
    const float* W_ih   = (const float*)d_in[13];
    const float* W_hh   = (const float*)d_in[14];
    const float* b_ih   = (const float*)d_in[15];
    const float* b_hh   = (const float*)d_in[16];
    const float* defnd  = (const float*)d_in[17];
    float* out = (float*)d_out;

    int S = in_sizes[2];
    int E = in_sizes[3];
    int N = in_sizes[6];
    int R = in_sizes[8] / DD;
    int stride = E + 1;

    float *p_sub, *p_bufG, *p_ghR, *p_objw;
    int* p_wcount;
    __half *p_smh, *p_sml, *p_subh, *p_subl, *p_r0h, *p_r0l, *p_relh, *p_rell;
    __half *p_rjh, *p_rjl, *p_wsub, *p_whh, *p_wih, *p_wobj;
    cudaGetSymbolAddress((void**)&p_sub,    g_sub);
    cudaGetSymbolAddress((void**)&p_bufG,   g_bufG);
    cudaGetSymbolAddress((void**)&p_ghR,    g_ghR);
    cudaGetSymbolAddress((void**)&p_objw,   g_objw);
    cudaGetSymbolAddress((void**)&p_wcount, g_wcount);
    cudaGetSymbolAddress((void**)&p_smh,    h_smask_h);
    cudaGetSymbolAddress((void**)&p_sml,    h_smask_l);
    cudaGetSymbolAddress((void**)&p_subh,   h_sub_h);
    cudaGetSymbolAddress((void**)&p_subl,   h_sub_l);
    cudaGetSymbolAddress((void**)&p_r0h,    h_r0_h);
    cudaGetSymbolAddress((void**)&p_r0l,    h_r0_l);
    cudaGetSymbolAddress((void**)&p_relh,   h_rel_h);
    cudaGetSymbolAddress((void**)&p_rell,   h_rel_l);
    cudaGetSymbolAddress((void**)&p_rjh,    h_rjw_h);
    cudaGetSymbolAddress((void**)&p_rjl,    h_rjw_l);
    cudaGetSymbolAddress((void**)&p_wsub,   h_Wsub);
    cudaGetSymbolAddress((void**)&p_whh,    h_Whh);
    cudaGetSymbolAddress((void**)&p_wih,    h_Wih);
    cudaGetSymbolAddress((void**)&p_wobj,   h_Wobj);

    cudaFuncSetAttribute(k_hgemm<0,0>, cudaFuncAttributeMaxDynamicSharedMemorySize, SMEM_DYN);
    cudaFuncSetAttribute(k_hgemm<1,0>, cudaFuncAttributeMaxDynamicSharedMemorySize, SMEM_DYN);
    cudaFuncSetAttribute(k_hgemm<1,1>, cudaFuncAttributeMaxDynamicSharedMemorySize, SMEM_DYN);

    // prepasses: weight / input conversions
    k_cvt_single<<<(DD * DD + 255) / 256, 256>>>(W_sub, p_wsub, DD * DD);
    k_cvt_single<<<(G3 * DD + 255) / 256, 256>>>(W_hh, p_whh, G3 * DD);
    k_cvt_single<<<(G3 * DD + 255) / 256, 256>>>(W_ih, p_wih, G3 * DD);
    k_cvt_single<<<(DD * DD + 255) / 256, 256>>>(W_obj, p_wobj, DD * DD);
    k_cvt_split <<<(S * DD + 255) / 256, 256>>>(smask, p_smh, p_sml, S * DD);
    k_cvt_split <<<(R * DD + 255) / 256, 256>>>(relemb, p_relh, p_rell, R * DD);

    // 1-3: timestamps
    k_init<<<(N + 255) / 256, 256>>>(N);
    k_seed<<<(S + 255) / 256, 256>>>(seeds, S, stride);
    k_edget<<<(E + 255) / 256, 256>>>(eheads, etails, E, stride);
    // 4: gi0 vector
    k_gi0<<<(G3 * 32 + 255) / 256, 256>>>(enc, W_ih, b_ih);
    // 5: sub = tanh(mask @ W_sub^T + b_sub)  [fp32 + fp16 dual]
    {
        dim3 g(DD / 128, (S + 127) / 128);
        k_hgemm<1,1><<<g, 256, SMEM_DYN>>>(p_smh, p_sml, p_wsub, b_sub,
                                           p_sub, p_subh, p_subl, S, DD, DD, nullptr);
    }
    // 6: gh0 = sub @ W_hh^T + b_hh
    {
        dim3 g(G3 / 128, (S + 127) / 128);
        k_hgemm<0,0><<<g, 256, SMEM_DYN>>>(p_subh, p_subl, p_whh, b_hh,
                                           p_bufG, nullptr, nullptr, S, G3, DD, nullptr);
    }
    // 7: r0 combine -> fp16 hi/lo
    k_r0<<<S, 256>>>(S);
    // 8: giH = r0 @ W_ih^T + b_ih
    {
        dim3 g(G3 / 128, (S + 127) / 128);
        k_hgemm<0,0><<<g, 256, SMEM_DYN>>>(p_r0h, p_r0l, p_wih, b_ih,
                                           p_bufG, nullptr, nullptr, S, G3, DD, nullptr);
    }
    // 9: ghR = rel @ W_hh^T + b_hh
    {
        dim3 g(G3 / 128, (R + 127) / 128);
        k_hgemm<0,0><<<g, 256, SMEM_DYN>>>(p_relh, p_rell, p_whh, b_hh,
                                           p_ghR, nullptr, nullptr, R, G3, DD, nullptr);
    }
    // 10: winner compaction
    k_compact<<<(E + 255) / 256, 256>>>(eheads, etails, E, stride);
    // 11: rj rows for winners -> fp16 hi/lo
    k_rj<<<E, 256>>>(eheads, etype, relemb);
    // 12: objw = tanh(rjw @ W_obj^T + b_obj), M clamped by wcount
    {
        dim3 g(DD / 128, (E + 127) / 128);
        k_hgemm<1,0><<<g, 256, SMEM_DYN>>>(p_rjh, p_rjl, p_wobj, b_obj,
                                           p_objw, nullptr, nullptr, E, DD, DD, p_wcount);
    }
    // 13: final gather
    k_final<<<N, 192>>>(n2n, oldnd, defnd, out, N, stride);
}

// round 6
// speedup vs baseline: 3.0078x; 1.2064x over previous
#include <cuda_runtime.h>
#include <cuda_fp16.h>
#include <math.h>
#include <stdint.h>

#define DD 768
#define G3 2304            // 3*DD
#define S_MAX 2048
#define E_MAX 32768
#define N_MAX 100000
#define R_MAX 1000

// ---------------- scratch (static __device__, no allocation) ----------------
__device__ float g_gi0[G3];
__device__ float g_sub[(size_t)S_MAX * DD];        // fp32 sub (k_r0 h-term, k_final)
__device__ float g_bufG[(size_t)S_MAX * G3];       // gh0 then giH
__device__ float g_ghR[(size_t)R_MAX * G3];
__device__ float g_objw[(size_t)E_MAX * DD];
__device__ int   g_best[N_MAX];
__device__ int   g_seedpos[N_MAX];
__device__ int   g_winedge[E_MAX];
__device__ int   g_winofnode[N_MAX];
__device__ int   g_wcount;

// fp16 operand arrays
__device__ __half h_smask[(size_t)S_MAX * DD];
__device__ __half h_subh [(size_t)S_MAX * DD];
__device__ __half h_r0h  [(size_t)S_MAX * DD];
__device__ __half h_relh [(size_t)R_MAX * DD];
__device__ __half h_rjwh [(size_t)E_MAX * DD];
__device__ __half h_Wsub[(size_t)DD * DD];
__device__ __half h_Whh [(size_t)G3 * DD];
__device__ __half h_Wih [(size_t)G3 * DD];
__device__ __half h_Wobj[(size_t)DD * DD];

// ---------------- helpers ----------------
__device__ __forceinline__ float fast_tanh(float x) {
    float y; asm("tanh.approx.f32 %0, %1;" : "=f"(y) : "f"(x)); return y;
}
__device__ __forceinline__ float fast_sigmoid(float x) {
    return 1.0f / (1.0f + __expf(-x));
}
__device__ __forceinline__ uint32_t smem_u32(const void* p) {
    uint32_t a;
    asm("{ .reg .u64 t; cvta.to.shared.u64 t, %1; cvt.u32.u64 %0, t; }" : "=r"(a) : "l"(p));
    return a;
}
#define SWZ64(o) ((o) ^ (((o) >> 3) & 0x30))

__device__ __forceinline__ void ldsm4(uint32_t addr, uint32_t* r) {
    asm volatile("ldmatrix.sync.aligned.m8n8.x4.shared.b16 {%0,%1,%2,%3}, [%4];"
                 : "=r"(r[0]), "=r"(r[1]), "=r"(r[2]), "=r"(r[3]) : "r"(addr));
}
__device__ __forceinline__ void mma_fp16(float* c, const uint32_t* a, const uint32_t* b) {
    asm volatile(
        "mma.sync.aligned.m16n8k16.row.col.f32.f16.f16.f32 "
        "{%0,%1,%2,%3}, {%4,%5,%6,%7}, {%8,%9}, {%0,%1,%2,%3};"
        : "+f"(c[0]), "+f"(c[1]), "+f"(c[2]), "+f"(c[3])
        : "r"(a[0]), "r"(a[1]), "r"(a[2]), "r"(a[3]), "r"(b[0]), "r"(b[1]));
}
__device__ __forceinline__ void cp16(uint32_t saddr, const void* g) {
    asm volatile("cp.async.cg.shared.global [%0], [%1], 16;" :: "r"(saddr), "l"(g));
}
__device__ __forceinline__ void cp_commit() {
    asm volatile("cp.async.commit_group;" ::: "memory");
}
template<int NN>
__device__ __forceinline__ void cp_wait() {
    asm volatile("cp.async.wait_group %0;" :: "n"(NN) : "memory");
}

// ---------------- small kernels ----------------
__global__ void k_init(int N) {
    int i = blockIdx.x * blockDim.x + threadIdx.x;
    if (i < N) { g_best[i] = -1; g_seedpos[i] = -1; }
    if (i == 0) g_wcount = 0;
}

__global__ void k_seed(const int* __restrict__ seeds, int S, int stride) {
    int s = blockIdx.x * blockDim.x + threadIdx.x;
    if (s >= S) return;
    int node = seeds[s];
    g_seedpos[node] = s;
    atomicMax(&g_best[node], s * stride);
}

__global__ void k_edget(const int* __restrict__ heads, const int* __restrict__ tails,
                        int E, int stride) {
    int e = blockIdx.x * blockDim.x + threadIdx.x;
    if (e >= E) return;
    int pos = g_seedpos[heads[e]];
    int t = pos * stride + 1 + e;
    atomicMax(&g_best[tails[e]], t);
}

__global__ void k_gi0(const float* __restrict__ enc, const float* __restrict__ W_ih,
                      const float* __restrict__ b_ih) {
    int warp = (blockIdx.x * blockDim.x + threadIdx.x) >> 5;
    int lane = threadIdx.x & 31;
    if (warp >= G3) return;
    const float* w = W_ih + (size_t)warp * DD;
    float s = 0.f;
    #pragma unroll 4
    for (int k = lane; k < DD; k += 32) s += enc[k] * w[k];
    #pragma unroll
    for (int off = 16; off; off >>= 1) s += __shfl_down_sync(0xffffffffu, s, off);
    if (lane == 0) g_gi0[warp] = s + b_ih[warp];
}

// fp32 -> fp16 conversion prepass (vectorized 4-wide)
__global__ void k_cvt(const float* __restrict__ x, __half* __restrict__ h, int n4) {
    int i = blockIdx.x * blockDim.x + threadIdx.x;
    if (i >= n4) return;
    float4 v = ((const float4*)x)[i];
    __half2 a = __halves2half2(__float2half(v.x), __float2half(v.y));
    __half2 b = __halves2half2(__float2half(v.z), __float2half(v.w));
    ((__half2*)h)[2 * i]     = a;
    ((__half2*)h)[2 * i + 1] = b;
}

// ---------------- fp16 HMMA GEMM (single pass, 3-stage cp.async) ----------------
// C[m,n] = epi( sum_k A[m,k]*W[n,k] + bias[n] ), A/W fp16 row-major [*,K].
// 128x128 CTA tile, BK=32. SMEM per stage: A,B tiles, 128 rows x 64B, SW64.
#define BK     32
#define TILEB  (128 * 64)        // 8192 B
#define STAGEB (2 * TILEB)       // 16384 B
#define NSTG   3
#define SMEM_DYN (NSTG * STAGEB) // 49152 B

template<int EPI, int DUAL>
__global__ void __launch_bounds__(256, 1)
k_hgemm(const __half* __restrict__ A, const __half* __restrict__ Bw,
        const float* __restrict__ bias,
        float* __restrict__ C, __half* __restrict__ Ch,
        int M, int N, int K, const int* __restrict__ mcount) {
    if (mcount) { int mc = *mcount; if (mc < M) M = mc; }
    int m0 = blockIdx.y * 128;
    int n0 = blockIdx.x * 128;
    if (m0 >= M) return;

    extern __shared__ __align__(1024) char sm[];
    uint32_t smb = smem_u32(sm);

    int tid = threadIdx.x, lane = tid & 31, wid = tid >> 5;
    int wm = wid >> 1, wn = wid & 1;
    int g = lane >> 3, lr = lane & 7;
    uint32_t xorm = (uint32_t)((lr & 6) << 3);

    // producer mapping: 2 16B chunks per thread per tile
    int q0 = tid * 2, q1 = tid * 2 + 1;
    int row0 = q0 >> 2, seg0 = q0 & 3;
    int row1 = q1 >> 2, seg1 = q1 & 3;
    uint32_t so0 = SWZ64((uint32_t)(row0 * 64 + seg0 * 16));
    uint32_t so1 = SWZ64((uint32_t)(row1 * 64 + seg1 * 16));
    size_t aoff0 = (size_t)min(m0 + row0, M - 1) * K + seg0 * 8;
    size_t aoff1 = (size_t)min(m0 + row1, M - 1) * K + seg1 * 8;
    size_t boff0 = (size_t)(n0 + row0) * K + seg0 * 8;
    size_t boff1 = (size_t)(n0 + row1) * K + seg1 * 8;

    const int NC = K / BK;

    auto issue = [&](int c) {
        uint32_t st = smb + (uint32_t)(c % NSTG) * STAGEB;
        int kc = c * BK;
        cp16(st + so0,         A  + aoff0 + kc);
        cp16(st + so1,         A  + aoff1 + kc);
        cp16(st + TILEB + so0, Bw + boff0 + kc);
        cp16(st + TILEB + so1, Bw + boff1 + kc);
        cp_commit();
    };

    float acc[2][8][4];
    #pragma unroll
    for (int i = 0; i < 2; i++)
        #pragma unroll
        for (int j = 0; j < 8; j++)
            #pragma unroll
            for (int q = 0; q < 4; q++) acc[i][j][q] = 0.f;

    issue(0);
    issue(1);

    for (int c = 0; c < NC; c++) {
        if (c + 2 < NC) { issue(c + 2); cp_wait<2>(); }
        else            { cp_wait<0>(); }
        __syncthreads();

        uint32_t stage = smb + (uint32_t)(c % NSTG) * STAGEB;
        #pragma unroll
        for (int ks = 0; ks < 2; ks++) {
            uint32_t kb = (uint32_t)(ks * 32);
            uint32_t ah[2][4], bb[4][4];
            #pragma unroll
            for (int mt = 0; mt < 2; mt++) {
                uint32_t off = (uint32_t)(wm * 32 + mt * 16 + (g & 1) * 8 + lr) * 64
                             + ((kb + (g >> 1) * 16) ^ xorm);
                ldsm4(stage + off, ah[mt]);
            }
            #pragma unroll
            for (int q = 0; q < 4; q++) {
                uint32_t off = (uint32_t)(wn * 64 + q * 16 + (g >> 1) * 8 + lr) * 64
                             + ((kb + (g & 1) * 16) ^ xorm);
                ldsm4(stage + TILEB + off, bb[q]);
            }
            #pragma unroll
            for (int mt = 0; mt < 2; mt++)
                #pragma unroll
                for (int q = 0; q < 4; q++) {
                    mma_fp16(acc[mt][2 * q],     ah[mt], bb[q]);
                    mma_fp16(acc[mt][2 * q + 1], ah[mt], bb[q] + 2);
                }
        }
        __syncthreads();
    }

    // ---- epilogue ----
    int lane4 = lane >> 2, lane2 = (lane & 3) * 2;
    #pragma unroll
    for (int mt = 0; mt < 2; mt++) {
        int r0 = m0 + wm * 32 + mt * 16 + lane4;
        #pragma unroll
        for (int q = 0; q < 8; q++) {
            int col = n0 + wn * 64 + q * 8 + lane2;
            float b0 = bias[col], b1 = bias[col + 1];
            float v0 = acc[mt][q][0] + b0, v1 = acc[mt][q][1] + b1;
            float v2 = acc[mt][q][2] + b0, v3 = acc[mt][q][3] + b1;
            if (EPI == 1) {
                v0 = fast_tanh(v0); v1 = fast_tanh(v1);
                v2 = fast_tanh(v2); v3 = fast_tanh(v3);
            }
            if (r0 < M) {
                *(float2*)(C + (size_t)r0 * N + col) = make_float2(v0, v1);
                if (DUAL)
                    *(__half2*)(Ch + (size_t)r0 * N + col) =
                        __halves2half2(__float2half(v0), __float2half(v1));
            }
            if (r0 + 8 < M) {
                *(float2*)(C + (size_t)(r0 + 8) * N + col) = make_float2(v2, v3);
                if (DUAL)
                    *(__half2*)(Ch + (size_t)(r0 + 8) * N + col) =
                        __halves2half2(__float2half(v2), __float2half(v3));
            }
        }
    }
}

// r0 = GRU combine -> fp16 (consumed only by GEMM step 8)
__global__ void k_r0(int S) {
    int s = blockIdx.x;
    if (s >= S) return;
    const float* gh = g_bufG + (size_t)s * G3;
    const float* hb = g_sub  + (size_t)s * DD;
    __half* rh = h_r0h + (size_t)s * DD;
    for (int d = threadIdx.x; d < DD; d += blockDim.x) {
        float r = fast_sigmoid(g_gi0[d]        + gh[d]);
        float z = fast_sigmoid(g_gi0[DD + d]   + gh[DD + d]);
        float n = fast_tanh   (g_gi0[2*DD + d] + r * gh[2*DD + d]);
        rh[d] = __float2half((1.f - z) * n + z * hb[d]);
    }
}

__global__ void k_compact(const int* __restrict__ heads, const int* __restrict__ tails,
                          int E, int stride) {
    int e = blockIdx.x * blockDim.x + threadIdx.x;
    if (e >= E) return;
    int pos = g_seedpos[heads[e]];
    int t = pos * stride + 1 + e;
    int tl = tails[e];
    if (g_best[tl] == t) {
        int w = atomicAdd(&g_wcount, 1);
        g_winedge[w] = e;
        g_winofnode[tl] = w;
    }
}

// rj rows for winners -> fp16 (consumed only by GEMM step 12)
__global__ void k_rj(const int* __restrict__ heads, const int* __restrict__ types,
                     const float* __restrict__ rel) {
    int w = blockIdx.x;
    if (w >= g_wcount) return;
    int e = g_winedge[w];
    int head = heads[e];
    int typ  = types[e];
    const float* gi = g_bufG + (size_t)head * G3;
    const float* gh = g_ghR  + (size_t)typ  * G3;
    const float* hv = rel    + (size_t)typ  * DD;
    __half* rh = h_rjwh + (size_t)w * DD;
    for (int d = threadIdx.x; d < DD; d += blockDim.x) {
        float r = fast_sigmoid(gi[d]        + gh[d]);
        float z = fast_sigmoid(gi[DD + d]   + gh[DD + d]);
        float n = fast_tanh   (gi[2*DD + d] + r * gh[2*DD + d]);
        rh[d] = __float2half((1.f - z) * n + z * hv[d]);
    }
}

__global__ void k_final(const int* __restrict__ n2n, const int* __restrict__ oldnd,
                        const float* __restrict__ defnd, float* __restrict__ out,
                        int N, int stride) {
    int node = blockIdx.x;
    if (node >= N) return;
    int id = n2n[oldnd[node]];
    int b  = g_best[id];
    const float4* src;
    if (b < 0) {
        src = (const float4*)(defnd + (size_t)node * DD);
    } else if (b % stride == 0) {
        src = (const float4*)(g_sub + (size_t)(b / stride) * DD);
    } else {
        src = (const float4*)(g_objw + (size_t)g_winofnode[id] * DD);
    }
    float4* dst = (float4*)(out + (size_t)node * DD);
    dst[threadIdx.x] = src[threadIdx.x];
}

// ---------------- launch ----------------
extern "C" void kernel_launch(void* const* d_in, const int* in_sizes, int n_in,
                              void* d_out, int out_size) {
    const float* enc    = (const float*)d_in[0];
    const float* smask  = (const float*)d_in[1];
    const int*   seeds  = (const int*)  d_in[2];
    const int*   eheads = (const int*)  d_in[3];
    const int*   etails = (const int*)  d_in[4];
    const int*   etype  = (const int*)  d_in[5];
    const int*   n2n    = (const int*)  d_in[6];
    const int*   oldnd  = (const int*)  d_in[7];
    const float* relemb = (const float*)d_in[8];
    const float* W_sub  = (const float*)d_in[9];
    const float* b_sub  = (const float*)d_in[10];
    const float* W_obj  = (const float*)d_in[11];
    const float* b_obj  = (const float*)d_in[12];
    const float* W_ih   = (const float*)d_in[13];
    const float* W_hh   = (const float*)d_in[14];
    const float* b_ih   = (const float*)d_in[15];
    const float* b_hh   = (const float*)d_in[16];
    const float* defnd  = (const float*)d_in[17];
    float* out = (float*)d_out;

    int S = in_sizes[2];
    int E = in_sizes[3];
    int N = in_sizes[6];
    int R = in_sizes[8] / DD;
    int stride = E + 1;

    float *p_sub, *p_bufG, *p_ghR, *p_objw;
    int* p_wcount;
    __half *p_smh, *p_subh, *p_r0h, *p_relh, *p_rjh, *p_wsub, *p_whh, *p_wih, *p_wobj;
    cudaGetSymbolAddress((void**)&p_sub,    g_sub);
    cudaGetSymbolAddress((void**)&p_bufG,   g_bufG);
    cudaGetSymbolAddress((void**)&p_ghR,    g_ghR);
    cudaGetSymbolAddress((void**)&p_objw,   g_objw);
    cudaGetSymbolAddress((void**)&p_wcount, g_wcount);
    cudaGetSymbolAddress((void**)&p_smh,    h_smask);
    cudaGetSymbolAddress((void**)&p_subh,   h_subh);
    cudaGetSymbolAddress((void**)&p_r0h,    h_r0h);
    cudaGetSymbolAddress((void**)&p_relh,   h_relh);
    cudaGetSymbolAddress((void**)&p_rjh,    h_rjwh);
    cudaGetSymbolAddress((void**)&p_wsub,   h_Wsub);
    cudaGetSymbolAddress((void**)&p_whh,    h_Whh);
    cudaGetSymbolAddress((void**)&p_wih,    h_Wih);
    cudaGetSymbolAddress((void**)&p_wobj,   h_Wobj);

    cudaFuncSetAttribute(k_hgemm<0,0>, cudaFuncAttributeMaxDynamicSharedMemorySize, SMEM_DYN);
    cudaFuncSetAttribute(k_hgemm<1,0>, cudaFuncAttributeMaxDynamicSharedMemorySize, SMEM_DYN);
    cudaFuncSetAttribute(k_hgemm<1,1>, cudaFuncAttributeMaxDynamicSharedMemorySize, SMEM_DYN);

    // prepasses: fp32 -> fp16 conversions (vectorized)
    k_cvt<<<(DD * DD / 4 + 255) / 256, 256>>>(W_sub,  p_wsub, DD * DD / 4);
    k_cvt<<<(G3 * DD / 4 + 255) / 256, 256>>>(W_hh,   p_whh,  G3 * DD / 4);
    k_cvt<<<(G3 * DD / 4 + 255) / 256, 256>>>(W_ih,   p_wih,  G3 * DD / 4);
    k_cvt<<<(DD * DD / 4 + 255) / 256, 256>>>(W_obj,  p_wobj, DD * DD / 4);
    k_cvt<<<(S * DD / 4 + 255) / 256, 256>>>(smask,  p_smh,  S * DD / 4);
    k_cvt<<<(R * DD / 4 + 255) / 256, 256>>>(relemb, p_relh, R * DD / 4);

    // 1-3: timestamps
    k_init<<<(N + 255) / 256, 256>>>(N);
    k_seed<<<(S + 255) / 256, 256>>>(seeds, S, stride);
    k_edget<<<(E + 255) / 256, 256>>>(eheads, etails, E, stride);
    // 4: gi0 vector
    k_gi0<<<(G3 * 32 + 255) / 256, 256>>>(enc, W_ih, b_ih);
    // 5: sub = tanh(mask @ W_sub^T + b_sub)  [fp32 + fp16 dual]
    {
        dim3 g(DD / 128, (S + 127) / 128);
        k_hgemm<1,1><<<g, 256, SMEM_DYN>>>(p_smh, p_wsub, b_sub,
                                           p_sub, p_subh, S, DD, DD, nullptr);
    }
    // 6: gh0 = sub @ W_hh^T + b_hh
    {
        dim3 g(G3 / 128, (S + 127) / 128);
        k_hgemm<0,0><<<g, 256, SMEM_DYN>>>(p_subh, p_whh, b_hh,
                                           p_bufG, nullptr, S, G3, DD, nullptr);
    }
    // 7: r0 combine -> fp16
    k_r0<<<S, 256>>>(S);
    // 8: giH = r0 @ W_ih^T + b_ih
    {
        dim3 g(G3 / 128, (S + 127) / 128);
        k_hgemm<0,0><<<g, 256, SMEM_DYN>>>(p_r0h, p_wih, b_ih,
                                           p_bufG, nullptr, S, G3, DD, nullptr);
    }
    // 9: ghR = rel @ W_hh^T + b_hh
    {
        dim3 g(G3 / 128, (R + 127) / 128);
        k_hgemm<0,0><<<g, 256, SMEM_DYN>>>(p_relh, p_whh, b_hh,
                                           p_ghR, nullptr, R, G3, DD, nullptr);
    }
    // 10: winner compaction
    k_compact<<<(E + 255) / 256, 256>>>(eheads, etails, E, stride);
    // 11: rj rows for winners -> fp16
    k_rj<<<E, 256>>>(eheads, etype, relemb);
    // 12: objw = tanh(rjw @ W_obj^T + b_obj), M clamped by wcount
    {
        dim3 g(DD / 128, (E + 127) / 128);
        k_hgemm<1,0><<<g, 256, SMEM_DYN>>>(p_rjh, p_wobj, b_obj,
                                           p_objw, nullptr, E, DD, DD, p_wcount);
    }
    // 13: final gather
    k_final<<<N, 192>>>(n2n, oldnd, defnd, out, N, stride);
}

// round 7
// speedup vs baseline: 3.0905x; 1.0275x over previous
#include <cuda_runtime.h>
#include <cuda_fp16.h>
#include <math.h>
#include <stdint.h>

#define DD 768
#define G3 2304            // 3*DD
#define S_MAX 2048
#define E_MAX 32768
#define N_MAX 100000
#define R_MAX 1000

// ---------------- scratch (static __device__, no allocation) ----------------
__device__ float g_gi0[G3];
__device__ float g_sub[(size_t)S_MAX * DD];        // fp32 sub (k_r0 h-term, k_final)
__device__ float g_objw[(size_t)E_MAX * DD];
__device__ int   g_best[N_MAX];
__device__ int   g_seedpos[N_MAX];
__device__ int   g_winedge[E_MAX];
__device__ int   g_winofnode[N_MAX];
__device__ int   g_wcount;

// fp16 arrays
__device__ __half h_bufG[(size_t)S_MAX * G3];      // gh0 then giH (fp16)
__device__ __half h_ghR [(size_t)R_MAX * G3];
__device__ __half h_smask[(size_t)S_MAX * DD];
__device__ __half h_subh [(size_t)S_MAX * DD];
__device__ __half h_r0h  [(size_t)S_MAX * DD];
__device__ __half h_relh [(size_t)R_MAX * DD];
__device__ __half h_rjwh [(size_t)E_MAX * DD];
__device__ __half h_Wsub[(size_t)DD * DD];
__device__ __half h_Whh [(size_t)G3 * DD];
__device__ __half h_Wih [(size_t)G3 * DD];
__device__ __half h_Wobj[(size_t)DD * DD];

// ---------------- helpers ----------------
__device__ __forceinline__ float fast_tanh(float x) {
    float y; asm("tanh.approx.f32 %0, %1;" : "=f"(y) : "f"(x)); return y;
}
__device__ __forceinline__ float fast_sigmoid(float x) {
    return 1.0f / (1.0f + __expf(-x));
}
__device__ __forceinline__ uint32_t smem_u32(const void* p) {
    uint32_t a;
    asm("{ .reg .u64 t; cvta.to.shared.u64 t, %1; cvt.u32.u64 %0, t; }" : "=r"(a) : "l"(p));
    return a;
}
#define SWZ64(o) ((o) ^ (((o) >> 3) & 0x30))

__device__ __forceinline__ void ldsm4(uint32_t addr, uint32_t* r) {
    asm volatile("ldmatrix.sync.aligned.m8n8.x4.shared.b16 {%0,%1,%2,%3}, [%4];"
                 : "=r"(r[0]), "=r"(r[1]), "=r"(r[2]), "=r"(r[3]) : "r"(addr));
}
__device__ __forceinline__ void mma_fp16(float* c, const uint32_t* a, const uint32_t* b) {
    asm volatile(
        "mma.sync.aligned.m16n8k16.row.col.f32.f16.f16.f32 "
        "{%0,%1,%2,%3}, {%4,%5,%6,%7}, {%8,%9}, {%0,%1,%2,%3};"
        : "+f"(c[0]), "+f"(c[1]), "+f"(c[2]), "+f"(c[3])
        : "r"(a[0]), "r"(a[1]), "r"(a[2]), "r"(a[3]), "r"(b[0]), "r"(b[1]));
}
__device__ __forceinline__ void cp16(uint32_t saddr, const void* g) {
    asm volatile("cp.async.cg.shared.global [%0], [%1], 16;" :: "r"(saddr), "l"(g));
}
__device__ __forceinline__ void cp_commit() {
    asm volatile("cp.async.commit_group;" ::: "memory");
}
template<int NN>
__device__ __forceinline__ void cp_wait() {
    asm volatile("cp.async.wait_group %0;" :: "n"(NN) : "memory");
}

// ---------------- small kernels ----------------
__global__ void k_init(int N) {
    int i = blockIdx.x * blockDim.x + threadIdx.x;
    if (i < N) { g_best[i] = -1; g_seedpos[i] = -1; }
    if (i == 0) g_wcount = 0;
}

__global__ void k_seed(const int* __restrict__ seeds, int S, int stride) {
    int s = blockIdx.x * blockDim.x + threadIdx.x;
    if (s >= S) return;
    int node = seeds[s];
    g_seedpos[node] = s;
    atomicMax(&g_best[node], s * stride);
}

__global__ void k_edget(const int* __restrict__ heads, const int* __restrict__ tails,
                        int E, int stride) {
    int e = blockIdx.x * blockDim.x + threadIdx.x;
    if (e >= E) return;
    int pos = g_seedpos[heads[e]];
    int t = pos * stride + 1 + e;
    atomicMax(&g_best[tails[e]], t);
}

__global__ void k_gi0(const float* __restrict__ enc, const float* __restrict__ W_ih,
                      const float* __restrict__ b_ih) {
    int warp = (blockIdx.x * blockDim.x + threadIdx.x) >> 5;
    int lane = threadIdx.x & 31;
    if (warp >= G3) return;
    const float* w = W_ih + (size_t)warp * DD;
    float s = 0.f;
    #pragma unroll 4
    for (int k = lane; k < DD; k += 32) s += enc[k] * w[k];
    #pragma unroll
    for (int off = 16; off; off >>= 1) s += __shfl_down_sync(0xffffffffu, s, off);
    if (lane == 0) g_gi0[warp] = s + b_ih[warp];
}

// merged fp32->fp16 conversion prepass for all 6 tensors (grid-stride, float4-wide)
struct CvtJob { const float* src; __half* dst; int n4; };
__global__ void k_cvt_all(CvtJob j0, CvtJob j1, CvtJob j2, CvtJob j3, CvtJob j4, CvtJob j5,
                          int total4) {
    for (int i = blockIdx.x * blockDim.x + threadIdx.x; i < total4;
         i += gridDim.x * blockDim.x) {
        int r = i;
        const float* s; __half* d;
        if (r < j0.n4)      { s = j0.src; d = j0.dst; }
        else { r -= j0.n4;
        if (r < j1.n4)      { s = j1.src; d = j1.dst; }
        else { r -= j1.n4;
        if (r < j2.n4)      { s = j2.src; d = j2.dst; }
        else { r -= j2.n4;
        if (r < j3.n4)      { s = j3.src; d = j3.dst; }
        else { r -= j3.n4;
        if (r < j4.n4)      { s = j4.src; d = j4.dst; }
        else { r -= j4.n4;    s = j5.src; d = j5.dst; } } } } }
        float4 v = ((const float4*)s)[r];
        ((__half2*)d)[2 * r]     = __halves2half2(__float2half(v.x), __float2half(v.y));
        ((__half2*)d)[2 * r + 1] = __halves2half2(__float2half(v.z), __float2half(v.w));
    }
}

// ---------------- fp16 HMMA GEMM (single pass, 5-stage cp.async) ----------------
// C[m,n] = epi( sum_k A[m,k]*W[n,k] + bias[n] ), A/W fp16 row-major [*,K].
// 128x128 CTA tile, BK=32. OMODE: 0 = fp32 C; 1 = fp32 C + fp16 Ch; 2 = fp16 Ch only.
#define BK     32
#define TILEB  (128 * 64)        // 8192 B
#define STAGEB (2 * TILEB)       // 16384 B
#define NSTG   5
#define SMEM_DYN (NSTG * STAGEB) // 81920 B

template<int EPI, int OMODE>
__global__ void __launch_bounds__(256, 1)
k_hgemm(const __half* __restrict__ A, const __half* __restrict__ Bw,
        const float* __restrict__ bias,
        float* __restrict__ C, __half* __restrict__ Ch,
        int M, int N, int K, const int* __restrict__ mcount) {
    if (mcount) { int mc = *mcount; if (mc < M) M = mc; }
    int m0 = blockIdx.y * 128;
    int n0 = blockIdx.x * 128;
    if (m0 >= M) return;

    extern __shared__ __align__(1024) char sm[];
    uint32_t smb = smem_u32(sm);

    int tid = threadIdx.x, lane = tid & 31, wid = tid >> 5;
    int wm = wid >> 1, wn = wid & 1;
    int g = lane >> 3, lr = lane & 7;
    uint32_t xorm = (uint32_t)((lr & 6) << 3);

    // producer mapping: 2 16B chunks per thread per tile
    int q0 = tid * 2, q1 = tid * 2 + 1;
    int row0 = q0 >> 2, seg0 = q0 & 3;
    int row1 = q1 >> 2, seg1 = q1 & 3;
    uint32_t so0 = SWZ64((uint32_t)(row0 * 64 + seg0 * 16));
    uint32_t so1 = SWZ64((uint32_t)(row1 * 64 + seg1 * 16));
    size_t aoff0 = (size_t)min(m0 + row0, M - 1) * K + seg0 * 8;
    size_t aoff1 = (size_t)min(m0 + row1, M - 1) * K + seg1 * 8;
    size_t boff0 = (size_t)(n0 + row0) * K + seg0 * 8;
    size_t boff1 = (size_t)(n0 + row1) * K + seg1 * 8;

    const int NC = K / BK;

    auto issue = [&](int c) {
        uint32_t st = smb + (uint32_t)(c % NSTG) * STAGEB;
        int kc = c * BK;
        cp16(st + so0,         A  + aoff0 + kc);
        cp16(st + so1,         A  + aoff1 + kc);
        cp16(st + TILEB + so0, Bw + boff0 + kc);
        cp16(st + TILEB + so1, Bw + boff1 + kc);
        cp_commit();
    };

    float acc[2][8][4];
    #pragma unroll
    for (int i = 0; i < 2; i++)
        #pragma unroll
        for (int j = 0; j < 8; j++)
            #pragma unroll
            for (int q = 0; q < 4; q++) acc[i][j][q] = 0.f;

    issue(0); issue(1); issue(2); issue(3);

    for (int c = 0; c < NC; c++) {
        if (c + 4 < NC) { issue(c + 4); cp_wait<4>(); }
        else            { cp_wait<0>(); }
        __syncthreads();

        uint32_t stage = smb + (uint32_t)(c % NSTG) * STAGEB;
        #pragma unroll
        for (int ks = 0; ks < 2; ks++) {
            uint32_t kb = (uint32_t)(ks * 32);
            uint32_t ah[2][4], bb[4][4];
            #pragma unroll
            for (int mt = 0; mt < 2; mt++) {
                uint32_t off = (uint32_t)(wm * 32 + mt * 16 + (g & 1) * 8 + lr) * 64
                             + ((kb + (g >> 1) * 16) ^ xorm);
                ldsm4(stage + off, ah[mt]);
            }
            #pragma unroll
            for (int q = 0; q < 4; q++) {
                uint32_t off = (uint32_t)(wn * 64 + q * 16 + (g >> 1) * 8 + lr) * 64
                             + ((kb + (g & 1) * 16) ^ xorm);
                ldsm4(stage + TILEB + off, bb[q]);
            }
            #pragma unroll
            for (int mt = 0; mt < 2; mt++)
                #pragma unroll
                for (int q = 0; q < 4; q++) {
                    mma_fp16(acc[mt][2 * q],     ah[mt], bb[q]);
                    mma_fp16(acc[mt][2 * q + 1], ah[mt], bb[q] + 2);
                }
        }
        __syncthreads();
    }

    // ---- epilogue ----
    int lane4 = lane >> 2, lane2 = (lane & 3) * 2;
    #pragma unroll
    for (int mt = 0; mt < 2; mt++) {
        int r0 = m0 + wm * 32 + mt * 16 + lane4;
        #pragma unroll
        for (int q = 0; q < 8; q++) {
            int col = n0 + wn * 64 + q * 8 + lane2;
            float b0 = bias[col], b1 = bias[col + 1];
            float v0 = acc[mt][q][0] + b0, v1 = acc[mt][q][1] + b1;
            float v2 = acc[mt][q][2] + b0, v3 = acc[mt][q][3] + b1;
            if (EPI == 1) {
                v0 = fast_tanh(v0); v1 = fast_tanh(v1);
                v2 = fast_tanh(v2); v3 = fast_tanh(v3);
            }
            if (r0 < M) {
                if (OMODE != 2)
                    *(float2*)(C + (size_t)r0 * N + col) = make_float2(v0, v1);
                if (OMODE >= 1)
                    *(__half2*)(Ch + (size_t)r0 * N + col) =
                        __halves2half2(__float2half(v0), __float2half(v1));
            }
            if (r0 + 8 < M) {
                if (OMODE != 2)
                    *(float2*)(C + (size_t)(r0 + 8) * N + col) = make_float2(v2, v3);
                if (OMODE >= 1)
                    *(__half2*)(Ch + (size_t)(r0 + 8) * N + col) =
                        __halves2half2(__float2half(v2), __float2half(v3));
            }
        }
    }
}

// r0 = GRU combine (fp16 gates) -> fp16
__global__ void k_r0(int S) {
    int s = blockIdx.x;
    if (s >= S) return;
    const __half* gh = h_bufG + (size_t)s * G3;
    const float*  hb = g_sub  + (size_t)s * DD;
    __half* rh = h_r0h + (size_t)s * DD;
    for (int d = threadIdx.x; d < DD; d += blockDim.x) {
        float r = fast_sigmoid(g_gi0[d]        + __half2float(gh[d]));
        float z = fast_sigmoid(g_gi0[DD + d]   + __half2float(gh[DD + d]));
        float n = fast_tanh   (g_gi0[2*DD + d] + r * __half2float(gh[2*DD + d]));
        rh[d] = __float2half((1.f - z) * n + z * hb[d]);
    }
}

__global__ void k_compact(const int* __restrict__ heads, const int* __restrict__ tails,
                          int E, int stride) {
    int e = blockIdx.x * blockDim.x + threadIdx.x;
    if (e >= E) return;
    int pos = g_seedpos[heads[e]];
    int t = pos * stride + 1 + e;
    int tl = tails[e];
    if (g_best[tl] == t) {
        int w = atomicAdd(&g_wcount, 1);
        g_winedge[w] = e;
        g_winofnode[tl] = w;
    }
}

// rj rows for winners (fp16 gates) -> fp16
__global__ void k_rj(const int* __restrict__ heads, const int* __restrict__ types,
                     const float* __restrict__ rel) {
    int w = blockIdx.x;
    if (w >= g_wcount) return;
    int e = g_winedge[w];
    int head = heads[e];
    int typ  = types[e];
    const __half* gi = h_bufG + (size_t)head * G3;
    const __half* gh = h_ghR  + (size_t)typ  * G3;
    const float*  hv = rel    + (size_t)typ  * DD;
    __half* rh = h_rjwh + (size_t)w * DD;
    for (int d = threadIdx.x; d < DD; d += blockDim.x) {
        float r = fast_sigmoid(__half2float(gi[d])        + __half2float(gh[d]));
        float z = fast_sigmoid(__half2float(gi[DD + d])   + __half2float(gh[DD + d]));
        float n = fast_tanh   (__half2float(gi[2*DD + d]) + r * __half2float(gh[2*DD + d]));
        rh[d] = __float2half((1.f - z) * n + z * hv[d]);
    }
}

__global__ void k_final(const int* __restrict__ n2n, const int* __restrict__ oldnd,
                        const float* __restrict__ defnd, float* __restrict__ out,
                        int N, int stride) {
    int node = blockIdx.x;
    if (node >= N) return;
    int id = n2n[oldnd[node]];
    int b  = g_best[id];
    const float4* src;
    if (b < 0) {
        src = (const float4*)(defnd + (size_t)node * DD);
    } else if (b % stride == 0) {
        src = (const float4*)(g_sub + (size_t)(b / stride) * DD);
    } else {
        src = (const float4*)(g_objw + (size_t)g_winofnode[id] * DD);
    }
    float4* dst = (float4*)(out + (size_t)node * DD);
    dst[threadIdx.x] = src[threadIdx.x];
}

// ---------------- launch ----------------
extern "C" void kernel_launch(void* const* d_in, const int* in_sizes, int n_in,
                              void* d_out, int out_size) {
    const float* enc    = (const float*)d_in[0];
    const float* smask  = (const float*)d_in[1];
    const int*   seeds  = (const int*)  d_in[2];
    const int*   eheads = (const int*)  d_in[3];
    const int*   etails = (const int*)  d_in[4];
    const int*   etype  = (const int*)  d_in[5];
    const int*   n2n    = (const int*)  d_in[6];
    const int*   oldnd  = (const int*)  d_in[7];
    const float* relemb = (const float*)d_in[8];
    const float* W_sub  = (const float*)d_in[9];
    const float* b_sub  = (const float*)d_in[10];
    const float* W_obj  = (const float*)d_in[11];
    const float* b_obj  = (const float*)d_in[12];
    const float* W_ih   = (const float*)d_in[13];
    const float* W_hh   = (const float*)d_in[14];
    const float* b_ih   = (const float*)d_in[15];
    const float* b_hh   = (const float*)d_in[16];
    const float* defnd  = (const float*)d_in[17];
    float* out = (float*)d_out;

    int S = in_sizes[2];
    int E = in_sizes[3];
    int N = in_sizes[6];
    int R = in_sizes[8] / DD;
    int stride = E + 1;

    float *p_sub, *p_objw;
    int* p_wcount;
    __half *p_bufG, *p_ghR, *p_smh, *p_subh, *p_r0h, *p_relh, *p_rjh;
    __half *p_wsub, *p_whh, *p_wih, *p_wobj;
    cudaGetSymbolAddress((void**)&p_sub,    g_sub);
    cudaGetSymbolAddress((void**)&p_objw,   g_objw);
    cudaGetSymbolAddress((void**)&p_wcount, g_wcount);
    cudaGetSymbolAddress((void**)&p_bufG,   h_bufG);
    cudaGetSymbolAddress((void**)&p_ghR,    h_ghR);
    cudaGetSymbolAddress((void**)&p_smh,    h_smask);
    cudaGetSymbolAddress((void**)&p_subh,   h_subh);
    cudaGetSymbolAddress((void**)&p_r0h,    h_r0h);
    cudaGetSymbolAddress((void**)&p_relh,   h_relh);
    cudaGetSymbolAddress((void**)&p_rjh,    h_rjwh);
    cudaGetSymbolAddress((void**)&p_wsub,   h_Wsub);
    cudaGetSymbolAddress((void**)&p_whh,    h_Whh);
    cudaGetSymbolAddress((void**)&p_wih,    h_Wih);
    cudaGetSymbolAddress((void**)&p_wobj,   h_Wobj);

    cudaFuncSetAttribute(k_hgemm<0,2>, cudaFuncAttributeMaxDynamicSharedMemorySize, SMEM_DYN);
    cudaFuncSetAttribute(k_hgemm<1,0>, cudaFuncAttributeMaxDynamicSharedMemorySize, SMEM_DYN);
    cudaFuncSetAttribute(k_hgemm<1,1>, cudaFuncAttributeMaxDynamicSharedMemorySize, SMEM_DYN);

    // launch 0: merged conversion prepass
    {
        CvtJob j0 = {W_sub,  p_wsub, DD * DD / 4};
        CvtJob j1 = {W_hh,   p_whh,  G3 * DD / 4};
        CvtJob j2 = {W_ih,   p_wih,  G3 * DD / 4};
        CvtJob j3 = {W_obj,  p_wobj, DD * DD / 4};
        CvtJob j4 = {smask,  p_smh,  S * DD / 4};
        CvtJob j5 = {relemb, p_relh, R * DD / 4};
        int total4 = j0.n4 + j1.n4 + j2.n4 + j3.n4 + j4.n4 + j5.n4;
        k_cvt_all<<<(total4 + 255) / 256, 256>>>(j0, j1, j2, j3, j4, j5, total4);
    }
    // launches 1-4
    k_init<<<(N + 255) / 256, 256>>>(N);
    k_seed<<<(S + 255) / 256, 256>>>(seeds, S, stride);
    k_edget<<<(E + 255) / 256, 256>>>(eheads, etails, E, stride);
    k_gi0<<<(G3 * 32 + 255) / 256, 256>>>(enc, W_ih, b_ih);
    // launch 5 (ncu -s 5 target): sub = tanh(mask @ W_sub^T + b_sub)  [fp32 + fp16 dual]
    {
        dim3 g(DD / 128, (S + 127) / 128);
        k_hgemm<1,1><<<g, 256, SMEM_DYN>>>(p_smh, p_wsub, b_sub,
                                           p_sub, p_subh, S, DD, DD, nullptr);
    }
    // gh0 = sub @ W_hh^T + b_hh  -> fp16 bufG
    {
        dim3 g(G3 / 128, (S + 127) / 128);
        k_hgemm<0,2><<<g, 256, SMEM_DYN>>>(p_subh, p_whh, b_hh,
                                           nullptr, p_bufG, S, G3, DD, nullptr);
    }
    // r0 combine -> fp16
    k_r0<<<S, 256>>>(S);
    // giH = r0 @ W_ih^T + b_ih -> fp16 bufG
    {
        dim3 g(G3 / 128, (S + 127) / 128);
        k_hgemm<0,2><<<g, 256, SMEM_DYN>>>(p_r0h, p_wih, b_ih,
                                           nullptr, p_bufG, S, G3, DD, nullptr);
    }
    // ghR = rel @ W_hh^T + b_hh -> fp16
    {
        dim3 g(G3 / 128, (R + 127) / 128);
        k_hgemm<0,2><<<g, 256, SMEM_DYN>>>(p_relh, p_whh, b_hh,
                                           nullptr, p_ghR, R, G3, DD, nullptr);
    }
    // winner compaction
    k_compact<<<(E + 255) / 256, 256>>>(eheads, etails, E, stride);
    // rj rows for winners -> fp16
    k_rj<<<E, 256>>>(eheads, etype, relemb);
    // objw = tanh(rjw @ W_obj^T + b_obj), M clamped by wcount
    {
        dim3 g(DD / 128, (E + 127) / 128);
        k_hgemm<1,0><<<g, 256, SMEM_DYN>>>(p_rjh, p_wobj, b_obj,
                                           p_objw, nullptr, E, DD, DD, p_wcount);
    }
    // final gather
    k_final<<<N, 192>>>(n2n, oldnd, defnd, out, N, stride);
}

// round 8
// speedup vs baseline: 3.5961x; 1.1636x over previous
#include <cuda_runtime.h>
#include <cuda_fp16.h>
#include <math.h>
#include <stdint.h>

#define DD 768
#define G3 2304            // 3*DD
#define S_MAX 2048
#define E_MAX 32768
#define N_MAX 100000
#define R_MAX 1000

// ---------------- scratch (static __device__, no allocation) ----------------
__device__ float g_gi0[G3];
__device__ float g_sub[(size_t)S_MAX * DD];        // fp32 sub (k_r0 h-term, k_final)
__device__ float g_objw[(size_t)E_MAX * DD];
__device__ int   g_best[N_MAX];
__device__ int   g_seedpos[N_MAX];
__device__ int   g_winedge[E_MAX];
__device__ int   g_winofnode[N_MAX];
__device__ int   g_wcount;

// fp16 arrays
__device__ __half h_bufG[(size_t)S_MAX * G3];      // gh0 then giH (fp16)
__device__ __half h_ghR [(size_t)R_MAX * G3];
__device__ __half h_smask[(size_t)S_MAX * DD];
__device__ __half h_subh [(size_t)S_MAX * DD];
__device__ __half h_r0h  [(size_t)S_MAX * DD];
__device__ __half h_relh [(size_t)R_MAX * DD];
__device__ __half h_rjwh [(size_t)E_MAX * DD];
__device__ __half h_Wsub[(size_t)DD * DD];
__device__ __half h_Whh [(size_t)G3 * DD];
__device__ __half h_Wih [(size_t)G3 * DD];
__device__ __half h_Wobj[(size_t)DD * DD];

// ---------------- helpers ----------------
__device__ __forceinline__ float fast_tanh(float x) {
    float y; asm("tanh.approx.f32 %0, %1;" : "=f"(y) : "f"(x)); return y;
}
__device__ __forceinline__ float fast_sigmoid(float x) {
    return 1.0f / (1.0f + __expf(-x));
}
__device__ __forceinline__ uint32_t smem_u32(const void* p) {
    uint32_t a;
    asm("{ .reg .u64 t; cvta.to.shared.u64 t, %1; cvt.u32.u64 %0, t; }" : "=r"(a) : "l"(p));
    return a;
}
#define SWZ64(o) ((o) ^ (((o) >> 3) & 0x30))

__device__ __forceinline__ void ldsm4(uint32_t addr, uint32_t* r) {
    asm volatile("ldmatrix.sync.aligned.m8n8.x4.shared.b16 {%0,%1,%2,%3}, [%4];"
                 : "=r"(r[0]), "=r"(r[1]), "=r"(r[2]), "=r"(r[3]) : "r"(addr));
}
__device__ __forceinline__ void mma_fp16(float* c, const uint32_t* a, const uint32_t* b) {
    asm volatile(
        "mma.sync.aligned.m16n8k16.row.col.f32.f16.f16.f32 "
        "{%0,%1,%2,%3}, {%4,%5,%6,%7}, {%8,%9}, {%0,%1,%2,%3};"
        : "+f"(c[0]), "+f"(c[1]), "+f"(c[2]), "+f"(c[3])
        : "r"(a[0]), "r"(a[1]), "r"(a[2]), "r"(a[3]), "r"(b[0]), "r"(b[1]));
}
__device__ __forceinline__ void cp16(uint32_t saddr, const void* g) {
    asm volatile("cp.async.cg.shared.global [%0], [%1], 16;" :: "r"(saddr), "l"(g));
}
__device__ __forceinline__ void cp_commit() {
    asm volatile("cp.async.commit_group;" ::: "memory");
}
template<int NN>
__device__ __forceinline__ void cp_wait() {
    asm volatile("cp.async.wait_group %0;" :: "n"(NN) : "memory");
}

// ---------------- small kernels ----------------
__global__ void k_init(int N) {
    int i = blockIdx.x * blockDim.x + threadIdx.x;
    if (i < N) { g_best[i] = -1; g_seedpos[i] = -1; }
    if (i == 0) g_wcount = 0;
}

__global__ void k_seed(const int* __restrict__ seeds, int S, int stride) {
    int s = blockIdx.x * blockDim.x + threadIdx.x;
    if (s >= S) return;
    int node = seeds[s];
    g_seedpos[node] = s;
    atomicMax(&g_best[node], s * stride);
}

__global__ void k_edget(const int* __restrict__ heads, const int* __restrict__ tails,
                        int E, int stride) {
    int e = blockIdx.x * blockDim.x + threadIdx.x;
    if (e >= E) return;
    int pos = g_seedpos[heads[e]];
    int t = pos * stride + 1 + e;
    atomicMax(&g_best[tails[e]], t);
}

__global__ void k_gi0(const float* __restrict__ enc, const float* __restrict__ W_ih,
                      const float* __restrict__ b_ih) {
    int warp = (blockIdx.x * blockDim.x + threadIdx.x) >> 5;
    int lane = threadIdx.x & 31;
    if (warp >= G3) return;
    const float* w = W_ih + (size_t)warp * DD;
    float s = 0.f;
    #pragma unroll 4
    for (int k = lane; k < DD; k += 32) s += enc[k] * w[k];
    #pragma unroll
    for (int off = 16; off; off >>= 1) s += __shfl_down_sync(0xffffffffu, s, off);
    if (lane == 0) g_gi0[warp] = s + b_ih[warp];
}

// merged fp32->fp16 conversion prepass (grid-stride, float4-wide)
struct CvtJob { const float* src; __half* dst; int n4; };
__global__ void k_cvt_all(CvtJob j0, CvtJob j1, CvtJob j2, CvtJob j3, CvtJob j4, CvtJob j5,
                          int total4) {
    for (int i = blockIdx.x * blockDim.x + threadIdx.x; i < total4;
         i += gridDim.x * blockDim.x) {
        int r = i;
        const float* s; __half* d;
        if (r < j0.n4)      { s = j0.src; d = j0.dst; }
        else { r -= j0.n4;
        if (r < j1.n4)      { s = j1.src; d = j1.dst; }
        else { r -= j1.n4;
        if (r < j2.n4)      { s = j2.src; d = j2.dst; }
        else { r -= j2.n4;
        if (r < j3.n4)      { s = j3.src; d = j3.dst; }
        else { r -= j3.n4;
        if (r < j4.n4)      { s = j4.src; d = j4.dst; }
        else { r -= j4.n4;    s = j5.src; d = j5.dst; } } } } }
        float4 v = ((const float4*)s)[r];
        ((__half2*)d)[2 * r]     = __halves2half2(__float2half(v.x), __float2half(v.y));
        ((__half2*)d)[2 * r + 1] = __halves2half2(__float2half(v.z), __float2half(v.w));
    }
}

// ---------------- fp16 HMMA GEMM (4-stage cp.async, 2 CTAs/SM) ----------------
// C[m,n] = epi( sum_k A[m,k]*W[n,k] + bias[n] ), A/W fp16 row-major [*,K].
// 128x128 CTA tile, BK=32. OMODE: 0 = fp32 C; 1 = fp32 C + fp16 Ch; 2 = fp16 Ch only.
// Optional second A segment (A2/Ch2) for row-blocks with m0 >= Ms (merged GEMMs).
#define BK     32
#define TILEB  (128 * 64)        // 8192 B
#define STAGEB (2 * TILEB)       // 16384 B
#define NSTG   4
#define SMEM_DYN (NSTG * STAGEB) // 65536 B

template<int EPI, int OMODE>
__global__ void __launch_bounds__(256, 2)
k_hgemm(const __half* A, const __half* A2, const __half* __restrict__ Bw,
        const float* __restrict__ bias,
        float* __restrict__ C, __half* Ch, __half* Ch2,
        int M, int N, int K, int Ms, const int* __restrict__ mcount) {
    if (mcount) { int mc = *mcount; if (mc < M) M = mc; }
    int m0 = blockIdx.y * 128;
    int n0 = blockIdx.x * 128;
    if (m0 >= M) return;
    if (A2 && m0 >= Ms) {           // second segment (Ms is 128-aligned)
        A  = A2  - (size_t)Ms * K;
        Ch = Ch2 - (size_t)Ms * N;
    }

    extern __shared__ __align__(1024) char sm[];
    uint32_t smb = smem_u32(sm);

    int tid = threadIdx.x, lane = tid & 31, wid = tid >> 5;
    int wm = wid >> 1, wn = wid & 1;
    int g = lane >> 3, lr = lane & 7;
    uint32_t xorm = (uint32_t)((lr & 6) << 3);

    // producer mapping: 2 16B chunks per thread per tile
    int q0 = tid * 2, q1 = tid * 2 + 1;
    int row0 = q0 >> 2, seg0 = q0 & 3;
    int row1 = q1 >> 2, seg1 = q1 & 3;
    uint32_t so0 = SWZ64((uint32_t)(row0 * 64 + seg0 * 16));
    uint32_t so1 = SWZ64((uint32_t)(row1 * 64 + seg1 * 16));
    size_t aoff0 = (size_t)min(m0 + row0, M - 1) * K + seg0 * 8;
    size_t aoff1 = (size_t)min(m0 + row1, M - 1) * K + seg1 * 8;
    size_t boff0 = (size_t)(n0 + row0) * K + seg0 * 8;
    size_t boff1 = (size_t)(n0 + row1) * K + seg1 * 8;

    const int NC = K / BK;

    auto issue = [&](int c) {
        uint32_t st = smb + (uint32_t)(c % NSTG) * STAGEB;
        int kc = c * BK;
        cp16(st + so0,         A  + aoff0 + kc);
        cp16(st + so1,         A  + aoff1 + kc);
        cp16(st + TILEB + so0, Bw + boff0 + kc);
        cp16(st + TILEB + so1, Bw + boff1 + kc);
        cp_commit();
    };

    float acc[2][8][4];
    #pragma unroll
    for (int i = 0; i < 2; i++)
        #pragma unroll
        for (int j = 0; j < 8; j++)
            #pragma unroll
            for (int q = 0; q < 4; q++) acc[i][j][q] = 0.f;

    issue(0); issue(1); issue(2);

    for (int c = 0; c < NC; c++) {
        if (c + 3 < NC) { issue(c + 3); cp_wait<3>(); }
        else            { cp_wait<0>(); }
        __syncthreads();

        uint32_t stage = smb + (uint32_t)(c % NSTG) * STAGEB;
        #pragma unroll
        for (int ks = 0; ks < 2; ks++) {
            uint32_t kb = (uint32_t)(ks * 32);
            uint32_t ah[2][4], bb[4][4];
            #pragma unroll
            for (int mt = 0; mt < 2; mt++) {
                uint32_t off = (uint32_t)(wm * 32 + mt * 16 + (g & 1) * 8 + lr) * 64
                             + ((kb + (g >> 1) * 16) ^ xorm);
                ldsm4(stage + off, ah[mt]);
            }
            #pragma unroll
            for (int q = 0; q < 4; q++) {
                uint32_t off = (uint32_t)(wn * 64 + q * 16 + (g >> 1) * 8 + lr) * 64
                             + ((kb + (g & 1) * 16) ^ xorm);
                ldsm4(stage + TILEB + off, bb[q]);
            }
            #pragma unroll
            for (int mt = 0; mt < 2; mt++)
                #pragma unroll
                for (int q = 0; q < 4; q++) {
                    mma_fp16(acc[mt][2 * q],     ah[mt], bb[q]);
                    mma_fp16(acc[mt][2 * q + 1], ah[mt], bb[q] + 2);
                }
        }
        __syncthreads();
    }

    // ---- epilogue ----
    int lane4 = lane >> 2, lane2 = (lane & 3) * 2;
    #pragma unroll
    for (int mt = 0; mt < 2; mt++) {
        int r0 = m0 + wm * 32 + mt * 16 + lane4;
        #pragma unroll
        for (int q = 0; q < 8; q++) {
            int col = n0 + wn * 64 + q * 8 + lane2;
            float b0 = bias[col], b1 = bias[col + 1];
            float v0 = acc[mt][q][0] + b0, v1 = acc[mt][q][1] + b1;
            float v2 = acc[mt][q][2] + b0, v3 = acc[mt][q][3] + b1;
            if (EPI == 1) {
                v0 = fast_tanh(v0); v1 = fast_tanh(v1);
                v2 = fast_tanh(v2); v3 = fast_tanh(v3);
            }
            if (r0 < M) {
                if (OMODE != 2)
                    *(float2*)(C + (size_t)r0 * N + col) = make_float2(v0, v1);
                if (OMODE >= 1)
                    *(__half2*)(Ch + (size_t)r0 * N + col) =
                        __halves2half2(__float2half(v0), __float2half(v1));
            }
            if (r0 + 8 < M) {
                if (OMODE != 2)
                    *(float2*)(C + (size_t)(r0 + 8) * N + col) = make_float2(v2, v3);
                if (OMODE >= 1)
                    *(__half2*)(Ch + (size_t)(r0 + 8) * N + col) =
                        __halves2half2(__float2half(v2), __float2half(v3));
            }
        }
    }
}

// r0 = GRU combine (fp16 gates) -> fp16
__global__ void k_r0(int S) {
    int s = blockIdx.x;
    if (s >= S) return;
    const __half* gh = h_bufG + (size_t)s * G3;
    const float*  hb = g_sub  + (size_t)s * DD;
    __half* rh = h_r0h + (size_t)s * DD;
    for (int d = threadIdx.x; d < DD; d += blockDim.x) {
        float r = fast_sigmoid(g_gi0[d]        + __half2float(gh[d]));
        float z = fast_sigmoid(g_gi0[DD + d]   + __half2float(gh[DD + d]));
        float n = fast_tanh   (g_gi0[2*DD + d] + r * __half2float(gh[2*DD + d]));
        rh[d] = __float2half((1.f - z) * n + z * hb[d]);
    }
}

__global__ void k_compact(const int* __restrict__ heads, const int* __restrict__ tails,
                          int E, int stride) {
    int e = blockIdx.x * blockDim.x + threadIdx.x;
    if (e >= E) return;
    int pos = g_seedpos[heads[e]];
    int t = pos * stride + 1 + e;
    int tl = tails[e];
    if (g_best[tl] == t) {
        int w = atomicAdd(&g_wcount, 1);
        g_winedge[w] = e;
        g_winofnode[tl] = w;
    }
}

// rj rows for winners (fp16 gates) -> fp16
__global__ void k_rj(const int* __restrict__ heads, const int* __restrict__ types,
                     const float* __restrict__ rel) {
    int w = blockIdx.x;
    if (w >= g_wcount) return;
    int e = g_winedge[w];
    int head = heads[e];
    int typ  = types[e];
    const __half* gi = h_bufG + (size_t)head * G3;
    const __half* gh = h_ghR  + (size_t)typ  * G3;
    const float*  hv = rel    + (size_t)typ  * DD;
    __half* rh = h_rjwh + (size_t)w * DD;
    for (int d = threadIdx.x; d < DD; d += blockDim.x) {
        float r = fast_sigmoid(__half2float(gi[d])        + __half2float(gh[d]));
        float z = fast_sigmoid(__half2float(gi[DD + d])   + __half2float(gh[DD + d]));
        float n = fast_tanh   (__half2float(gi[2*DD + d]) + r * __half2float(gh[2*DD + d]));
        rh[d] = __float2half((1.f - z) * n + z * hv[d]);
    }
}

__global__ void k_final(const int* __restrict__ n2n, const int* __restrict__ oldnd,
                        const float* __restrict__ defnd, float* __restrict__ out,
                        int N, int stride) {
    int node = blockIdx.x;
    if (node >= N) return;
    int id = n2n[oldnd[node]];
    int b  = g_best[id];
    const float4* src;
    if (b < 0) {
        src = (const float4*)(defnd + (size_t)node * DD);
    } else if (b % stride == 0) {
        src = (const float4*)(g_sub + (size_t)(b / stride) * DD);
    } else {
        src = (const float4*)(g_objw + (size_t)g_winofnode[id] * DD);
    }
    float4* dst = (float4*)(out + (size_t)node * DD);
    dst[threadIdx.x] = src[threadIdx.x];
}

// ---------------- launch ----------------
extern "C" void kernel_launch(void* const* d_in, const int* in_sizes, int n_in,
                              void* d_out, int out_size) {
    const float* enc    = (const float*)d_in[0];
    const float* smask  = (const float*)d_in[1];
    const int*   seeds  = (const int*)  d_in[2];
    const int*   eheads = (const int*)  d_in[3];
    const int*   etails = (const int*)  d_in[4];
    const int*   etype  = (const int*)  d_in[5];
    const int*   n2n    = (const int*)  d_in[6];
    const int*   oldnd  = (const int*)  d_in[7];
    const float* relemb = (const float*)d_in[8];
    const float* W_sub  = (const float*)d_in[9];
    const float* b_sub  = (const float*)d_in[10];
    const float* W_obj  = (const float*)d_in[11];
    const float* b_obj  = (const float*)d_in[12];
    const float* W_ih   = (const float*)d_in[13];
    const float* W_hh   = (const float*)d_in[14];
    const float* b_ih   = (const float*)d_in[15];
    const float* b_hh   = (const float*)d_in[16];
    const float* defnd  = (const float*)d_in[17];
    float* out = (float*)d_out;

    int S = in_sizes[2];
    int E = in_sizes[3];
    int N = in_sizes[6];
    int R = in_sizes[8] / DD;
    int stride = E + 1;

    float *p_sub, *p_objw;
    int* p_wcount;
    __half *p_bufG, *p_ghR, *p_smh, *p_subh, *p_r0h, *p_relh, *p_rjh;
    __half *p_wsub, *p_whh, *p_wih, *p_wobj;
    cudaGetSymbolAddress((void**)&p_sub,    g_sub);
    cudaGetSymbolAddress((void**)&p_objw,   g_objw);
    cudaGetSymbolAddress((void**)&p_wcount, g_wcount);
    cudaGetSymbolAddress((void**)&p_bufG,   h_bufG);
    cudaGetSymbolAddress((void**)&p_ghR,    h_ghR);
    cudaGetSymbolAddress((void**)&p_smh,    h_smask);
    cudaGetSymbolAddress((void**)&p_subh,   h_subh);
    cudaGetSymbolAddress((void**)&p_r0h,    h_r0h);
    cudaGetSymbolAddress((void**)&p_relh,   h_relh);
    cudaGetSymbolAddress((void**)&p_rjh,    h_rjwh);
    cudaGetSymbolAddress((void**)&p_wsub,   h_Wsub);
    cudaGetSymbolAddress((void**)&p_whh,    h_Whh);
    cudaGetSymbolAddress((void**)&p_wih,    h_Wih);
    cudaGetSymbolAddress((void**)&p_wobj,   h_Wobj);

    cudaFuncSetAttribute(k_hgemm<0,2>, cudaFuncAttributeMaxDynamicSharedMemorySize, SMEM_DYN);
    cudaFuncSetAttribute(k_hgemm<1,0>, cudaFuncAttributeMaxDynamicSharedMemorySize, SMEM_DYN);
    cudaFuncSetAttribute(k_hgemm<1,1>, cudaFuncAttributeMaxDynamicSharedMemorySize, SMEM_DYN);

    // launch 0: merged conversion prepass
    {
        CvtJob j0 = {W_sub,  p_wsub, DD * DD / 4};
        CvtJob j1 = {W_hh,   p_whh,  G3 * DD / 4};
        CvtJob j2 = {W_ih,   p_wih,  G3 * DD / 4};
        CvtJob j3 = {W_obj,  p_wobj, DD * DD / 4};
        CvtJob j4 = {smask,  p_smh,  S * DD / 4};
        CvtJob j5 = {relemb, p_relh, R * DD / 4};
        int total4 = j0.n4 + j1.n4 + j2.n4 + j3.n4 + j4.n4 + j5.n4;
        k_cvt_all<<<(total4 + 255) / 256, 256>>>(j0, j1, j2, j3, j4, j5, total4);
    }
    // launches 1-4
    k_init<<<(N + 255) / 256, 256>>>(N);
    k_seed<<<(S + 255) / 256, 256>>>(seeds, S, stride);
    k_edget<<<(E + 255) / 256, 256>>>(eheads, etails, E, stride);
    k_gi0<<<(G3 * 32 + 255) / 256, 256>>>(enc, W_ih, b_ih);
    // launch 5: sub = tanh(mask @ W_sub^T + b_sub)  [fp32 + fp16 dual]
    {
        dim3 g(DD / 128, (S + 127) / 128);
        k_hgemm<1,1><<<g, 256, SMEM_DYN>>>(p_smh, nullptr, p_wsub, b_sub,
                                           p_sub, p_subh, nullptr,
                                           S, DD, DD, 1 << 30, nullptr);
    }
    // merged: [sub; rel] @ W_hh^T + b_hh -> [bufG; ghR] (fp16)
    {
        int yb = S / 128 + (R + 127) / 128;
        dim3 g(G3 / 128, yb);
        k_hgemm<0,2><<<g, 256, SMEM_DYN>>>(p_subh, p_relh, p_whh, b_hh,
                                           nullptr, p_bufG, p_ghR,
                                           S + R, G3, DD, S, nullptr);
    }
    // r0 combine -> fp16
    k_r0<<<S, 256>>>(S);
    // giH = r0 @ W_ih^T + b_ih -> fp16 bufG
    {
        dim3 g(G3 / 128, (S + 127) / 128);
        k_hgemm<0,2><<<g, 256, SMEM_DYN>>>(p_r0h, nullptr, p_wih, b_ih,
                                           nullptr, p_bufG, nullptr,
                                           S, G3, DD, 1 << 30, nullptr);
    }
    // winner compaction
    k_compact<<<(E + 255) / 256, 256>>>(eheads, etails, E, stride);
    // rj rows for winners -> fp16
    k_rj<<<E, 256>>>(eheads, etype, relemb);
    // objw = tanh(rjw @ W_obj^T + b_obj), M clamped by wcount
    {
        dim3 g(DD / 128, (E + 127) / 128);
        k_hgemm<1,0><<<g, 256, SMEM_DYN>>>(p_rjh, nullptr, p_wobj, b_obj,
                                           p_objw, nullptr, nullptr,
                                           E, DD, DD, 1 << 30, p_wcount);
    }
    // final gather
    k_final<<<N, 192>>>(n2n, oldnd, defnd, out, N, stride);
}

// round 9
// speedup vs baseline: 3.8171x; 1.0615x over previous
#include <cuda_runtime.h>
#include <cuda_fp16.h>
#include <math.h>
#include <stdint.h>

#define DD 768
#define G3 2304            // 3*DD
#define S_MAX 2048
#define E_MAX 32768
#define N_MAX 100000
#define R_MAX 1000

// ---------------- scratch (static __device__, no allocation) ----------------
__device__ float g_gi0[G3];
__device__ float g_sub[(size_t)S_MAX * DD];        // fp32 sub (k_r0 h-term, k_final)
__device__ float g_objw[(size_t)E_MAX * DD];
__device__ int   g_best[N_MAX];                    // 0 = unwritten, else timestamp+1
__device__ int   g_seedpos[N_MAX];
__device__ int   g_winedge[E_MAX];
__device__ int   g_winofnode[N_MAX];
__device__ int   g_wcount;

// fp16 arrays
__device__ __half h_bufG[(size_t)S_MAX * G3];      // gh0 then giH (fp16)
__device__ __half h_ghR [(size_t)R_MAX * G3];
__device__ __half h_smask[(size_t)S_MAX * DD];
__device__ __half h_subh [(size_t)S_MAX * DD];
__device__ __half h_r0h  [(size_t)S_MAX * DD];
__device__ __half h_relh [(size_t)R_MAX * DD];
__device__ __half h_rjwh [(size_t)E_MAX * DD];
__device__ __half h_Wsub[(size_t)DD * DD];
__device__ __half h_Whh [(size_t)G3 * DD];
__device__ __half h_Wih [(size_t)G3 * DD];
__device__ __half h_Wobj[(size_t)DD * DD];

// ---------------- helpers ----------------
__device__ __forceinline__ float fast_tanh(float x) {
    float y; asm("tanh.approx.f32 %0, %1;" : "=f"(y) : "f"(x)); return y;
}
__device__ __forceinline__ float fast_sigmoid(float x) {
    return 1.0f / (1.0f + __expf(-x));
}
__device__ __forceinline__ uint32_t smem_u32(const void* p) {
    uint32_t a;
    asm("{ .reg .u64 t; cvta.to.shared.u64 t, %1; cvt.u32.u64 %0, t; }" : "=r"(a) : "l"(p));
    return a;
}
#define SWZ64(o) ((o) ^ (((o) >> 3) & 0x30))

__device__ __forceinline__ void ldsm4(uint32_t addr, uint32_t* r) {
    asm volatile("ldmatrix.sync.aligned.m8n8.x4.shared.b16 {%0,%1,%2,%3}, [%4];"
                 : "=r"(r[0]), "=r"(r[1]), "=r"(r[2]), "=r"(r[3]) : "r"(addr));
}
__device__ __forceinline__ void mma_fp16(float* c, const uint32_t* a, const uint32_t* b) {
    asm volatile(
        "mma.sync.aligned.m16n8k16.row.col.f32.f16.f16.f32 "
        "{%0,%1,%2,%3}, {%4,%5,%6,%7}, {%8,%9}, {%0,%1,%2,%3};"
        : "+f"(c[0]), "+f"(c[1]), "+f"(c[2]), "+f"(c[3])
        : "r"(a[0]), "r"(a[1]), "r"(a[2]), "r"(a[3]), "r"(b[0]), "r"(b[1]));
}
__device__ __forceinline__ void cp16(uint32_t saddr, const void* g) {
    asm volatile("cp.async.cg.shared.global [%0], [%1], 16;" :: "r"(saddr), "l"(g));
}
__device__ __forceinline__ void cp_commit() {
    asm volatile("cp.async.commit_group;" ::: "memory");
}
template<int NN>
__device__ __forceinline__ void cp_wait() {
    asm volatile("cp.async.wait_group %0;" :: "n"(NN) : "memory");
}

// ---------------- small kernels ----------------
__global__ void k_seed(const int* __restrict__ seeds, int S, int stride) {
    int s = blockIdx.x * blockDim.x + threadIdx.x;
    if (s >= S) return;
    int node = seeds[s];
    g_seedpos[node] = s;
    atomicMax(&g_best[node], s * stride + 1);
}

__global__ void k_edget(const int* __restrict__ heads, const int* __restrict__ tails,
                        int E, int stride) {
    int e = blockIdx.x * blockDim.x + threadIdx.x;
    if (e >= E) return;
    int pos = g_seedpos[heads[e]];
    int t = pos * stride + 2 + e;
    atomicMax(&g_best[tails[e]], t);
}

__global__ void k_gi0(const float* __restrict__ enc, const float* __restrict__ W_ih,
                      const float* __restrict__ b_ih) {
    int warp = (blockIdx.x * blockDim.x + threadIdx.x) >> 5;
    int lane = threadIdx.x & 31;
    if (warp >= G3) return;
    const float* w = W_ih + (size_t)warp * DD;
    float s = 0.f;
    #pragma unroll 4
    for (int k = lane; k < DD; k += 32) s += enc[k] * w[k];
    #pragma unroll
    for (int off = 16; off; off >>= 1) s += __shfl_down_sync(0xffffffffu, s, off);
    if (lane == 0) g_gi0[warp] = s + b_ih[warp];
}

// merged fp32->fp16 conversion prepass (grid-stride, float4-wide)
struct CvtJob { const float* src; __half* dst; int n4; };
__global__ void k_cvt_all(CvtJob j0, CvtJob j1, CvtJob j2, CvtJob j3, CvtJob j4, CvtJob j5,
                          int total4) {
    for (int i = blockIdx.x * blockDim.x + threadIdx.x; i < total4;
         i += gridDim.x * blockDim.x) {
        int r = i;
        const float* s; __half* d;
        if (r < j0.n4)      { s = j0.src; d = j0.dst; }
        else { r -= j0.n4;
        if (r < j1.n4)      { s = j1.src; d = j1.dst; }
        else { r -= j1.n4;
        if (r < j2.n4)      { s = j2.src; d = j2.dst; }
        else { r -= j2.n4;
        if (r < j3.n4)      { s = j3.src; d = j3.dst; }
        else { r -= j3.n4;
        if (r < j4.n4)      { s = j4.src; d = j4.dst; }
        else { r -= j4.n4;    s = j5.src; d = j5.dst; } } } } }
        float4 v = ((const float4*)s)[r];
        ((__half2*)d)[2 * r]     = __halves2half2(__float2half(v.x), __float2half(v.y));
        ((__half2*)d)[2 * r + 1] = __halves2half2(__float2half(v.z), __float2half(v.w));
    }
}

// ---------------- fp16 HMMA GEMM (4-stage cp.async, 1 sync/iter, 2 CTAs/SM) ----
#define BK     32
#define TILEB  (128 * 64)        // 8192 B
#define STAGEB (2 * TILEB)       // 16384 B
#define NSTG   4
#define SMEM_DYN (NSTG * STAGEB) // 65536 B

template<int EPI, int OMODE>
__global__ void __launch_bounds__(256, 2)
k_hgemm(const __half* A, const __half* A2, const __half* __restrict__ Bw,
        const float* __restrict__ bias,
        float* __restrict__ C, __half* Ch, __half* Ch2,
        int M, int N, int K, int Ms, const int* __restrict__ mcount) {
    if (mcount) { int mc = *mcount; if (mc < M) M = mc; }
    int m0 = blockIdx.y * 128;
    int n0 = blockIdx.x * 128;
    if (m0 >= M) return;
    if (A2 && m0 >= Ms) {           // second segment (Ms is 128-aligned)
        A  = A2  - (size_t)Ms * K;
        Ch = Ch2 - (size_t)Ms * N;
    }

    extern __shared__ __align__(1024) char sm[];
    uint32_t smb = smem_u32(sm);

    int tid = threadIdx.x, lane = tid & 31, wid = tid >> 5;
    int wm = wid >> 1, wn = wid & 1;
    int g = lane >> 3, lr = lane & 7;
    uint32_t xorm = (uint32_t)((lr & 6) << 3);

    // producer mapping: 2 16B chunks per thread per tile
    int q0 = tid * 2, q1 = tid * 2 + 1;
    int row0 = q0 >> 2, seg0 = q0 & 3;
    int row1 = q1 >> 2, seg1 = q1 & 3;
    uint32_t so0 = SWZ64((uint32_t)(row0 * 64 + seg0 * 16));
    uint32_t so1 = SWZ64((uint32_t)(row1 * 64 + seg1 * 16));
    size_t aoff0 = (size_t)min(m0 + row0, M - 1) * K + seg0 * 8;
    size_t aoff1 = (size_t)min(m0 + row1, M - 1) * K + seg1 * 8;
    size_t boff0 = (size_t)(n0 + row0) * K + seg0 * 8;
    size_t boff1 = (size_t)(n0 + row1) * K + seg1 * 8;

    const int NC = K / BK;

    auto issue = [&](int c) {
        uint32_t st = smb + (uint32_t)(c % NSTG) * STAGEB;
        int kc = c * BK;
        cp16(st + so0,         A  + aoff0 + kc);
        cp16(st + so1,         A  + aoff1 + kc);
        cp16(st + TILEB + so0, Bw + boff0 + kc);
        cp16(st + TILEB + so1, Bw + boff1 + kc);
        cp_commit();
    };

    float acc[2][8][4];
    #pragma unroll
    for (int i = 0; i < 2; i++)
        #pragma unroll
        for (int j = 0; j < 8; j++)
            #pragma unroll
            for (int q = 0; q < 4; q++) acc[i][j][q] = 0.f;

    issue(0); issue(1); issue(2);

    for (int c = 0; c < NC; c++) {
        // stage c ready for THIS thread:
        if (c + 2 < NC)      cp_wait<2>();
        else if (c + 1 < NC) cp_wait<1>();
        else                 cp_wait<0>();
        // single barrier: publishes stage c to all threads AND proves all
        // warps finished reading stage (c-1)%NSTG (their iter c-1 MMAs).
        __syncthreads();
        if (c + 3 < NC) issue(c + 3);   // writes stage (c-1)%NSTG — safe post-barrier

        uint32_t stage = smb + (uint32_t)(c % NSTG) * STAGEB;
        #pragma unroll
        for (int ks = 0; ks < 2; ks++) {
            uint32_t kb = (uint32_t)(ks * 32);
            uint32_t ah[2][4], bb[4][4];
            #pragma unroll
            for (int mt = 0; mt < 2; mt++) {
                uint32_t off = (uint32_t)(wm * 32 + mt * 16 + (g & 1) * 8 + lr) * 64
                             + ((kb + (g >> 1) * 16) ^ xorm);
                ldsm4(stage + off, ah[mt]);
            }
            #pragma unroll
            for (int q = 0; q < 4; q++) {
                uint32_t off = (uint32_t)(wn * 64 + q * 16 + (g >> 1) * 8 + lr) * 64
                             + ((kb + (g & 1) * 16) ^ xorm);
                ldsm4(stage + TILEB + off, bb[q]);
            }
            #pragma unroll
            for (int mt = 0; mt < 2; mt++)
                #pragma unroll
                for (int q = 0; q < 4; q++) {
                    mma_fp16(acc[mt][2 * q],     ah[mt], bb[q]);
                    mma_fp16(acc[mt][2 * q + 1], ah[mt], bb[q] + 2);
                }
        }
    }

    // ---- epilogue ----
    int lane4 = lane >> 2, lane2 = (lane & 3) * 2;
    #pragma unroll
    for (int mt = 0; mt < 2; mt++) {
        int r0 = m0 + wm * 32 + mt * 16 + lane4;
        #pragma unroll
        for (int q = 0; q < 8; q++) {
            int col = n0 + wn * 64 + q * 8 + lane2;
            float b0 = bias[col], b1 = bias[col + 1];
            float v0 = acc[mt][q][0] + b0, v1 = acc[mt][q][1] + b1;
            float v2 = acc[mt][q][2] + b0, v3 = acc[mt][q][3] + b1;
            if (EPI == 1) {
                v0 = fast_tanh(v0); v1 = fast_tanh(v1);
                v2 = fast_tanh(v2); v3 = fast_tanh(v3);
            }
            if (r0 < M) {
                if (OMODE != 2)
                    *(float2*)(C + (size_t)r0 * N + col) = make_float2(v0, v1);
                if (OMODE >= 1)
                    *(__half2*)(Ch + (size_t)r0 * N + col) =
                        __halves2half2(__float2half(v0), __float2half(v1));
            }
            if (r0 + 8 < M) {
                if (OMODE != 2)
                    *(float2*)(C + (size_t)(r0 + 8) * N + col) = make_float2(v2, v3);
                if (OMODE >= 1)
                    *(__half2*)(Ch + (size_t)(r0 + 8) * N + col) =
                        __halves2half2(__float2half(v2), __float2half(v3));
            }
        }
    }
}

// r0 = GRU combine (fp16 gates, half2-vectorized) -> fp16
__global__ void k_r0(int S) {
    int s = blockIdx.x;
    if (s >= S) return;
    const __half2* gh = (const __half2*)(h_bufG + (size_t)s * G3);
    const float2*  hb = (const float2*)(g_sub  + (size_t)s * DD);
    const float2*  gi = (const float2*)g_gi0;
    __half2* rh = (__half2*)(h_r0h + (size_t)s * DD);
    const int H = DD / 2;
    for (int d = threadIdx.x; d < H; d += blockDim.x) {
        float2 i_r = gi[d], i_z = gi[H + d], i_n = gi[2 * H + d];
        float2 hr = __half22float2(gh[d]);
        float2 hz = __half22float2(gh[H + d]);
        float2 hn = __half22float2(gh[2 * H + d]);
        float2 hv = hb[d];
        float r0_ = fast_sigmoid(i_r.x + hr.x), r1_ = fast_sigmoid(i_r.y + hr.y);
        float z0 = fast_sigmoid(i_z.x + hz.x), z1 = fast_sigmoid(i_z.y + hz.y);
        float n0 = fast_tanh(i_n.x + r0_ * hn.x), n1 = fast_tanh(i_n.y + r1_ * hn.y);
        rh[d] = __halves2half2(__float2half((1.f - z0) * n0 + z0 * hv.x),
                               __float2half((1.f - z1) * n1 + z1 * hv.y));
    }
}

__global__ void k_compact(const int* __restrict__ heads, const int* __restrict__ tails,
                          int E, int stride) {
    int e = blockIdx.x * blockDim.x + threadIdx.x;
    if (e >= E) return;
    int pos = g_seedpos[heads[e]];
    int t = pos * stride + 2 + e;
    int tl = tails[e];
    if (g_best[tl] == t) {
        int w = atomicAdd(&g_wcount, 1);
        g_winedge[w] = e;
        g_winofnode[tl] = w;
    }
}

// rj rows for winners (fp16 gates, half2-vectorized) -> fp16
__global__ void k_rj(const int* __restrict__ heads, const int* __restrict__ types,
                     const float* __restrict__ rel) {
    int w = blockIdx.x;
    if (w >= g_wcount) return;
    int e = g_winedge[w];
    int head = heads[e];
    int typ  = types[e];
    const __half2* gi = (const __half2*)(h_bufG + (size_t)head * G3);
    const __half2* gh = (const __half2*)(h_ghR  + (size_t)typ  * G3);
    const float2*  hv = (const float2*)(rel     + (size_t)typ  * DD);
    __half2* rh = (__half2*)(h_rjwh + (size_t)w * DD);
    const int H = DD / 2;
    for (int d = threadIdx.x; d < H; d += blockDim.x) {
        float2 ir = __half22float2(gi[d]);
        float2 iz = __half22float2(gi[H + d]);
        float2 in_ = __half22float2(gi[2 * H + d]);
        float2 hr = __half22float2(gh[d]);
        float2 hz = __half22float2(gh[H + d]);
        float2 hn = __half22float2(gh[2 * H + d]);
        float2 h2 = hv[d];
        float r0_ = fast_sigmoid(ir.x + hr.x), r1_ = fast_sigmoid(ir.y + hr.y);
        float z0 = fast_sigmoid(iz.x + hz.x), z1 = fast_sigmoid(iz.y + hz.y);
        float n0 = fast_tanh(in_.x + r0_ * hn.x), n1 = fast_tanh(in_.y + r1_ * hn.y);
        rh[d] = __halves2half2(__float2half((1.f - z0) * n0 + z0 * h2.x),
                               __float2half((1.f - z1) * n1 + z1 * h2.y));
    }
}

__global__ void k_final(const int* __restrict__ n2n, const int* __restrict__ oldnd,
                        const float* __restrict__ defnd, float* __restrict__ out,
                        int N, int stride) {
    int node = blockIdx.x;
    if (node >= N) return;
    int id = n2n[oldnd[node]];
    int b  = g_best[id];
    const float4* src;
    if (b == 0) {
        src = (const float4*)(defnd + (size_t)node * DD);
    } else if ((b - 1) % stride == 0) {
        src = (const float4*)(g_sub + (size_t)((b - 1) / stride) * DD);
    } else {
        src = (const float4*)(g_objw + (size_t)g_winofnode[id] * DD);
    }
    float4* dst = (float4*)(out + (size_t)node * DD);
    dst[threadIdx.x] = src[threadIdx.x];
}

// ---------------- launch ----------------
extern "C" void kernel_launch(void* const* d_in, const int* in_sizes, int n_in,
                              void* d_out, int out_size) {
    const float* enc    = (const float*)d_in[0];
    const float* smask  = (const float*)d_in[1];
    const int*   seeds  = (const int*)  d_in[2];
    const int*   eheads = (const int*)  d_in[3];
    const int*   etails = (const int*)  d_in[4];
    const int*   etype  = (const int*)  d_in[5];
    const int*   n2n    = (const int*)  d_in[6];
    const int*   oldnd  = (const int*)  d_in[7];
    const float* relemb = (const float*)d_in[8];
    const float* W_sub  = (const float*)d_in[9];
    const float* b_sub  = (const float*)d_in[10];
    const float* W_obj  = (const float*)d_in[11];
    const float* b_obj  = (const float*)d_in[12];
    const float* W_ih   = (const float*)d_in[13];
    const float* W_hh   = (const float*)d_in[14];
    const float* b_ih   = (const float*)d_in[15];
    const float* b_hh   = (const float*)d_in[16];
    const float* defnd  = (const float*)d_in[17];
    float* out = (float*)d_out;

    int S = in_sizes[2];
    int E = in_sizes[3];
    int N = in_sizes[6];
    int R = in_sizes[8] / DD;
    int stride = E + 1;

    float *p_sub, *p_objw;
    int *p_wcount, *p_best, *p_seedpos;
    __half *p_bufG, *p_ghR, *p_smh, *p_subh, *p_r0h, *p_relh, *p_rjh;
    __half *p_wsub, *p_whh, *p_wih, *p_wobj;
    cudaGetSymbolAddress((void**)&p_sub,     g_sub);
    cudaGetSymbolAddress((void**)&p_objw,    g_objw);
    cudaGetSymbolAddress((void**)&p_wcount,  g_wcount);
    cudaGetSymbolAddress((void**)&p_best,    g_best);
    cudaGetSymbolAddress((void**)&p_seedpos, g_seedpos);
    cudaGetSymbolAddress((void**)&p_bufG,    h_bufG);
    cudaGetSymbolAddress((void**)&p_ghR,     h_ghR);
    cudaGetSymbolAddress((void**)&p_smh,     h_smask);
    cudaGetSymbolAddress((void**)&p_subh,    h_subh);
    cudaGetSymbolAddress((void**)&p_r0h,     h_r0h);
    cudaGetSymbolAddress((void**)&p_relh,    h_relh);
    cudaGetSymbolAddress((void**)&p_rjh,     h_rjwh);
    cudaGetSymbolAddress((void**)&p_wsub,    h_Wsub);
    cudaGetSymbolAddress((void**)&p_whh,     h_Whh);
    cudaGetSymbolAddress((void**)&p_wih,     h_Wih);
    cudaGetSymbolAddress((void**)&p_wobj,    h_Wobj);

    cudaFuncSetAttribute(k_hgemm<0,2>, cudaFuncAttributeMaxDynamicSharedMemorySize, SMEM_DYN);
    cudaFuncSetAttribute(k_hgemm<1,0>, cudaFuncAttributeMaxDynamicSharedMemorySize, SMEM_DYN);
    cudaFuncSetAttribute(k_hgemm<1,1>, cudaFuncAttributeMaxDynamicSharedMemorySize, SMEM_DYN);

    // init via memset (graph-capturable, no kernel)
    cudaMemsetAsync(p_best, 0, (size_t)N * sizeof(int));
    cudaMemsetAsync(p_seedpos, 0xFF, (size_t)N * sizeof(int));
    cudaMemsetAsync(p_wcount, 0, sizeof(int));

    // merged conversion prepass
    {
        CvtJob j0 = {W_sub,  p_wsub, DD * DD / 4};
        CvtJob j1 = {W_hh,   p_whh,  G3 * DD / 4};
        CvtJob j2 = {W_ih,   p_wih,  G3 * DD / 4};
        CvtJob j3 = {W_obj,  p_wobj, DD * DD / 4};
        CvtJob j4 = {smask,  p_smh,  S * DD / 4};
        CvtJob j5 = {relemb, p_relh, R * DD / 4};
        int total4 = j0.n4 + j1.n4 + j2.n4 + j3.n4 + j4.n4 + j5.n4;
        k_cvt_all<<<(total4 + 255) / 256, 256>>>(j0, j1, j2, j3, j4, j5, total4);
    }
    // scatter chain
    k_seed<<<(S + 255) / 256, 256>>>(seeds, S, stride);
    k_edget<<<(E + 255) / 256, 256>>>(eheads, etails, E, stride);
    k_gi0<<<(G3 * 32 + 255) / 256, 256>>>(enc, W_ih, b_ih);
    // sub = tanh(mask @ W_sub^T + b_sub)  [fp32 + fp16 dual]
    {
        dim3 g(DD / 128, (S + 127) / 128);
        k_hgemm<1,1><<<g, 256, SMEM_DYN>>>(p_smh, nullptr, p_wsub, b_sub,
                                           p_sub, p_subh, nullptr,
                                           S, DD, DD, 1 << 30, nullptr);
    }
    // merged: [sub; rel] @ W_hh^T + b_hh -> [bufG; ghR] (fp16)
    {
        int yb = S / 128 + (R + 127) / 128;
        dim3 g(G3 / 128, yb);
        k_hgemm<0,2><<<g, 256, SMEM_DYN>>>(p_subh, p_relh, p_whh, b_hh,
                                           nullptr, p_bufG, p_ghR,
                                           S + R, G3, DD, S, nullptr);
    }
    // r0 combine -> fp16
    k_r0<<<S, 192>>>(S);
    // giH = r0 @ W_ih^T + b_ih -> fp16 bufG
    {
        dim3 g(G3 / 128, (S + 127) / 128);
        k_hgemm<0,2><<<g, 256, SMEM_DYN>>>(p_r0h, nullptr, p_wih, b_ih,
                                           nullptr, p_bufG, nullptr,
                                           S, G3, DD, 1 << 30, nullptr);
    }
    // winner compaction
    k_compact<<<(E + 255) / 256, 256>>>(eheads, etails, E, stride);
    // rj rows for winners -> fp16
    k_rj<<<E, 192>>>(eheads, etype, relemb);
    // objw = tanh(rjw @ W_obj^T + b_obj), M clamped by wcount
    {
        dim3 g(DD / 128, (E + 127) / 128);
        k_hgemm<1,0><<<g, 256, SMEM_DYN>>>(p_rjh, nullptr, p_wobj, b_obj,
                                           p_objw, nullptr, nullptr,
                                           E, DD, DD, 1 << 30, p_wcount);
    }
    // final gather
    k_final<<<N, 192>>>(n2n, oldnd, defnd, out, N, stride);
}